// round 10
// baseline (speedup 1.0000x reference)
#include <cuda_runtime.h>

// Problem constants
#define BB 4
#define LL 512
#define DD 1024
#define HH 16
#define DH 64
#define BH (BB*HH)            // 64
#define OUT_ELEMS (BB*LL*DD)  // 2097152

// Scratch (no allocations allowed -> __device__ globals)
// Values stored tf32-rounded (bit patterns of cvt.rna.tf32) so consumers can
// feed smem bits directly to mma without per-fragment cvt.
__device__ float g_q[BB*HH*LL*DH];    // [b][h][l][dh]   (rounded)
__device__ float g_k[BB*HH*LL*DH];    // [b][h][dh][l]   (rounded, transposed)
__device__ float g_v[BB*HH*LL*DH];    // [b][h][l][dh]   (rounded)
__device__ float g_ctx[BB*LL*DD];     // (rounded)

// ---------------------------------------------------------------------------
// tf32 helpers (mma.sync m16n8k8, row.col, f32 accum)
// ---------------------------------------------------------------------------
__device__ __forceinline__ unsigned f2tf(float x) {
    unsigned y; asm("cvt.rna.tf32.f32 %0, %1;" : "=r"(y) : "f"(x)); return y;
}
__device__ __forceinline__ uint4 cvt4(float4 v) {
    uint4 u; u.x = f2tf(v.x); u.y = f2tf(v.y); u.z = f2tf(v.z); u.w = f2tf(v.w);
    return u;
}
__device__ __forceinline__ void mma8(float* d, const unsigned* a,
                                     const unsigned* b, const float* c) {
    asm volatile(
        "mma.sync.aligned.m16n8k8.row.col.f32.tf32.tf32.f32 "
        "{%0,%1,%2,%3}, {%4,%5,%6,%7}, {%8,%9}, {%10,%11,%12,%13};"
        : "=f"(d[0]), "=f"(d[1]), "=f"(d[2]), "=f"(d[3])
        : "r"(a[0]), "r"(a[1]), "r"(a[2]), "r"(a[3]),
          "r"(b[0]), "r"(b[1]),
          "f"(c[0]), "f"(c[1]), "f"(c[2]), "f"(c[3]));
}

__device__ __forceinline__ unsigned smem_u32(const void* p) {
    return (unsigned)__cvta_generic_to_shared(p);
}
__device__ __forceinline__ void cpa16(unsigned dst, const void* src) {
    asm volatile("cp.async.cg.shared.global [%0], [%1], 16;" :: "r"(dst), "l"(src));
}
#define CP_COMMIT() asm volatile("cp.async.commit_group;")
#define CP_WAIT0()  asm volatile("cp.async.wait_group 0;")

// Smem strides (elements), conflict-free fragment reads:
//   As stride 20  (mod 32 = 4), Bs stride 136 (mod 32 = 8), Bs64 stride 72
#define AS_S 20
#define BS_S 136
#define BS64_S 72

struct PArg { const float* A; const float* W; const float* bias;
              float* out; float scale; int mode; };
struct PArgs { PArg p[3]; };

// ---------------------------------------------------------------------------
// Projection GEMM: C = A(2048x1024) @ W(1024x1024) + bias, scale.
// mode 0: out[m][n] raw; mode 1: [b][h][l][dh] tf32-rounded;
// mode 2: [b][h][dh][l] tf32-rounded.
// 128x128 tile, BK=16, 2-stage cp.async (STATIC smem), cvt at fragment read.
// 8 warps (2m x 4n), warp tile 64x32.
// ---------------------------------------------------------------------------
__global__ __launch_bounds__(256, 2) void proj_tf32(PArgs args)
{
    __shared__ __align__(16) float Asf[2][128 * AS_S];
    __shared__ __align__(16) float Bsf[2][16 * BS_S];

    const int K = 1024, N = 1024, NIT = 64;

    PArg pa = args.p[blockIdx.z];
    const float* __restrict__ A = pa.A;
    const float* __restrict__ W = pa.W;

    int t = threadIdx.x;
    int m0 = blockIdx.y * 128, n0 = blockIdx.x * 128;
    int wid = t >> 5, lane = t & 31;
    int wm = (wid >> 2) * 64, wn = (wid & 3) * 32;
    int g = lane >> 2, tg = lane & 3;

    int a_r = t >> 2;            // 0..63 (+64)
    int a_c = (t & 3) * 4;
    int b_r = t >> 5;            // 0..7 (+8)
    int b_c = (t & 31) * 4;

    const float* a_src = &A[(m0 + a_r) * K + a_c];
    const float* w_src = &W[b_r * N + n0 + b_c];
    unsigned a_dst = smem_u32(&Asf[0][a_r * AS_S + a_c]);
    unsigned b_dst = smem_u32(&Bsf[0][b_r * BS_S + b_c]);
    const unsigned a_stg = 128 * AS_S * 4;
    const unsigned b_stg = 16 * BS_S * 4;

    float acc[4][4][4];
    #pragma unroll
    for (int i = 0; i < 4; i++)
        #pragma unroll
        for (int j = 0; j < 4; j++)
            #pragma unroll
            for (int e = 0; e < 4; e++) acc[i][j][e] = 0.f;

    // tile 0 -> stage 0
    cpa16(a_dst,                  a_src);
    cpa16(a_dst + 64 * AS_S * 4,  a_src + 64 * K);
    cpa16(b_dst,                  w_src);
    cpa16(b_dst + 8 * BS_S * 4,   w_src + 8 * N);
    CP_COMMIT();

    for (int i = 0; i < NIT; i++) {
        CP_WAIT0();
        __syncthreads();   // stage i ready for all; all warps done reading stage i^1

        int ki = i + 1;
        if (ki < NIT) {
            unsigned s = (unsigned)(ki & 1);
            cpa16(a_dst + s * a_stg,                 a_src + ki * 16);
            cpa16(a_dst + s * a_stg + 64 * AS_S * 4, a_src + ki * 16 + 64 * K);
            cpa16(b_dst + s * b_stg,                 w_src + ki * 16 * N);
            cpa16(b_dst + s * b_stg + 8 * BS_S * 4,  w_src + ki * 16 * N + 8 * N);
            CP_COMMIT();
        }

        const float* Ap = Asf[i & 1];
        const float* Bp = Bsf[i & 1];

        #pragma unroll
        for (int kk = 0; kk < 16; kk += 8) {
            unsigned af[4][4], bf[4][2];
            #pragma unroll
            for (int mf = 0; mf < 4; mf++) {
                int row = wm + mf * 16 + g;
                af[mf][0] = f2tf(Ap[row * AS_S + kk + tg]);
                af[mf][1] = f2tf(Ap[(row + 8) * AS_S + kk + tg]);
                af[mf][2] = f2tf(Ap[row * AS_S + kk + 4 + tg]);
                af[mf][3] = f2tf(Ap[(row + 8) * AS_S + kk + 4 + tg]);
            }
            #pragma unroll
            for (int nf = 0; nf < 4; nf++) {
                int col = wn + nf * 8 + g;
                bf[nf][0] = f2tf(Bp[(kk + tg) * BS_S + col]);
                bf[nf][1] = f2tf(Bp[(kk + 4 + tg) * BS_S + col]);
            }
            #pragma unroll
            for (int mf = 0; mf < 4; mf++)
                #pragma unroll
                for (int nf = 0; nf < 4; nf++)
                    mma8(acc[mf][nf], af[mf], bf[nf], acc[mf][nf]);
        }
    }

    #pragma unroll
    for (int mf = 0; mf < 4; mf++) {
        #pragma unroll
        for (int nf = 0; nf < 4; nf++) {
            int col = n0 + wn + nf * 8 + 2 * tg;
            float2 b2 = *(const float2*)&pa.bias[col];
            #pragma unroll
            for (int rr = 0; rr < 2; rr++) {
                int m = m0 + wm + mf * 16 + g + rr * 8;
                float vx = (acc[mf][nf][rr * 2 + 0] + b2.x) * pa.scale;
                float vy = (acc[mf][nf][rr * 2 + 1] + b2.y) * pa.scale;
                if (pa.mode == 0) {
                    *(float2*)&pa.out[m * 1024 + col] = make_float2(vx, vy);
                } else {
                    // round so downstream consumers can skip cvt
                    vx = __uint_as_float(f2tf(vx));
                    vy = __uint_as_float(f2tf(vy));
                    int b = m >> 9, l = m & 511;
                    int h = col >> 6, dh = col & 63;
                    if (pa.mode == 1) {
                        *(float2*)&pa.out[((b * HH + h) * LL + l) * DH + dh] =
                            make_float2(vx, vy);
                    } else {
                        pa.out[((b * HH + h) * DH + dh) * LL + l] = vx;
                        pa.out[((b * HH + h) * DH + dh + 1) * LL + l] = vy;
                    }
                }
            }
        }
    }
}

// ---------------------------------------------------------------------------
// qk: scores[bh][i][j] = q[bh][i][:] . kT[bh][:][j]  (M=N=512, K=64 per bh)
// 2-stage cp.async, static smem. q/kT are pre-rounded -> fragments read as
// raw bits, zero cvt.
// ---------------------------------------------------------------------------
__global__ __launch_bounds__(256, 2) void qk_tf32(float* __restrict__ scores)
{
    __shared__ __align__(16) unsigned Asq[2][128 * AS_S];
    __shared__ __align__(16) unsigned Bsq[2][16 * BS_S];

    const int NIT = 4;   // K=64 / 16

    int t = threadIdx.x;
    int bh = blockIdx.z;
    const float* __restrict__ Q  = g_q + bh * LL * DH;   // [l][dh]
    const float* __restrict__ KT = g_k + bh * LL * DH;   // [dh][l]
    int m0 = blockIdx.y * 128, n0 = blockIdx.x * 128;
    int wid = t >> 5, lane = t & 31;
    int wm = (wid >> 2) * 64, wn = (wid & 3) * 32;
    int g = lane >> 2, tg = lane & 3;

    int a_r = t >> 2, a_c = (t & 3) * 4;
    int b_r = t >> 5, b_c = (t & 31) * 4;

    const float* a_src = &Q[(m0 + a_r) * DH + a_c];
    const float* k_src = &KT[b_r * LL + n0 + b_c];
    unsigned a_dst = smem_u32(&Asq[0][a_r * AS_S + a_c]);
    unsigned b_dst = smem_u32(&Bsq[0][b_r * BS_S + b_c]);
    const unsigned a_stg = 128 * AS_S * 4;
    const unsigned b_stg = 16 * BS_S * 4;

    float acc[4][4][4];
    #pragma unroll
    for (int i = 0; i < 4; i++)
        #pragma unroll
        for (int j = 0; j < 4; j++)
            #pragma unroll
            for (int e = 0; e < 4; e++) acc[i][j][e] = 0.f;

    cpa16(a_dst,                 a_src);
    cpa16(a_dst + 64 * AS_S * 4, a_src + 64 * DH);
    cpa16(b_dst,                 k_src);
    cpa16(b_dst + 8 * BS_S * 4,  k_src + 8 * LL);
    CP_COMMIT();

    for (int i = 0; i < NIT; i++) {
        CP_WAIT0();
        __syncthreads();

        int ki = i + 1;
        if (ki < NIT) {
            unsigned s = (unsigned)(ki & 1);
            cpa16(a_dst + s * a_stg,                 a_src + ki * 16);
            cpa16(a_dst + s * a_stg + 64 * AS_S * 4, a_src + ki * 16 + 64 * DH);
            cpa16(b_dst + s * b_stg,                 k_src + ki * 16 * LL);
            cpa16(b_dst + s * b_stg + 8 * BS_S * 4,  k_src + ki * 16 * LL + 8 * LL);
            CP_COMMIT();
        }

        const unsigned* Ap = Asq[i & 1];
        const unsigned* Bp = Bsq[i & 1];

        #pragma unroll
        for (int kk = 0; kk < 16; kk += 8) {
            unsigned af[4][4], bf[4][2];
            #pragma unroll
            for (int mf = 0; mf < 4; mf++) {
                int row = wm + mf * 16 + g;
                af[mf][0] = Ap[row * AS_S + kk + tg];
                af[mf][1] = Ap[(row + 8) * AS_S + kk + tg];
                af[mf][2] = Ap[row * AS_S + kk + 4 + tg];
                af[mf][3] = Ap[(row + 8) * AS_S + kk + 4 + tg];
            }
            #pragma unroll
            for (int nf = 0; nf < 4; nf++) {
                int col = wn + nf * 8 + g;
                bf[nf][0] = Bp[(kk + tg) * BS_S + col];
                bf[nf][1] = Bp[(kk + 4 + tg) * BS_S + col];
            }
            #pragma unroll
            for (int mf = 0; mf < 4; mf++)
                #pragma unroll
                for (int nf = 0; nf < 4; nf++)
                    mma8(acc[mf][nf], af[mf], bf[nf], acc[mf][nf]);
        }
    }

    float* srow = scores + (size_t)bh * LL * LL;
    #pragma unroll
    for (int mf = 0; mf < 4; mf++)
        #pragma unroll
        for (int nf = 0; nf < 4; nf++) {
            int col = n0 + wn + nf * 8 + 2 * tg;
            #pragma unroll
            for (int rr = 0; rr < 2; rr++) {
                int m = m0 + wm + mf * 16 + g + rr * 8;
                *(float2*)&srow[m * LL + col] =
                    make_float2(acc[mf][nf][rr * 2], acc[mf][nf][rr * 2 + 1]);
            }
        }
}

// ---------------------------------------------------------------------------
// Fused ast + mask + softmax. Block (i, b), 128 threads.  (unchanged, proven)
// Thread (wid, g, tg) owns rows h=g and h=g+8, cols jt*128+wid*32+nf*8+2tg+{0,1}.
// ---------------------------------------------------------------------------
__global__ __launch_bounds__(128) void astsm_tf32(
    const int* __restrict__ mat, const float* __restrict__ semb,
    const float* __restrict__ vemb, float* __restrict__ attn,
    const unsigned char* __restrict__ mask)
{
    __shared__ __align__(16) unsigned qs[16 * 68];
    __shared__ __align__(16) unsigned pe[128 * 68];
    __shared__ unsigned char mks[512];
    __shared__ float redmx[16 * 4];
    __shared__ float redsm[16 * 4];

    int i = blockIdx.x, b = blockIdx.y;
    int t = threadIdx.x;
    int wid = t >> 5, lane = t & 31;
    int g = lane >> 2, tg = lane & 3;

    for (int idx = t; idx < HH * DH; idx += 128) {
        int h = idx >> 6, d = idx & 63;
        qs[h * 68 + d] = f2tf(g_q[((b * HH + h) * LL + i) * DH + d]);
    }
    *(uchar4*)&mks[t * 4] = *(const uchar4*)&mask[b * LL + t * 4];
    __syncthreads();

    unsigned af[8][4];
    #pragma unroll
    for (int ks = 0; ks < 8; ks++) {
        af[ks][0] = qs[g * 68 + ks * 8 + tg];
        af[ks][1] = qs[(g + 8) * 68 + ks * 8 + tg];
        af[ks][2] = qs[g * 68 + ks * 8 + 4 + tg];
        af[ks][3] = qs[(g + 8) * 68 + ks * 8 + 4 + tg];
    }

    const int* mrow = mat + (b * LL + i) * LL;
    float sc[4][4][4];   // [jt][nf][e]

    for (int jt = 0; jt < 4; jt++) {
        int j0 = jt * 128;
        __syncthreads();
        {
            int j = j0 + t;
            int id = mrow[j];
            const float* e = ((j & 1) ? vemb : semb) + id * DH;
            #pragma unroll
            for (int s = 0; s < 64; s += 4)
                *(uint4*)&pe[t * 68 + s] = cvt4(*(const float4*)&e[s]);
        }
        __syncthreads();

        #pragma unroll
        for (int nf = 0; nf < 4; nf++)
            #pragma unroll
            for (int e = 0; e < 4; e++) sc[jt][nf][e] = 0.f;

        #pragma unroll
        for (int ks = 0; ks < 8; ks++) {
            #pragma unroll
            for (int nf = 0; nf < 4; nf++) {
                int jj = wid * 32 + nf * 8 + g;
                unsigned bf[2];
                bf[0] = pe[jj * 68 + ks * 8 + tg];
                bf[1] = pe[jj * 68 + ks * 8 + 4 + tg];
                mma8(sc[jt][nf], af[ks], bf, sc[jt][nf]);
            }
        }
    }

    size_t base0 = (((size_t)(b * HH + g) * LL + i) * LL);
    size_t base1 = (((size_t)(b * HH + g + 8) * LL + i) * LL);
    #pragma unroll
    for (int jt = 0; jt < 4; jt++)
        #pragma unroll
        for (int nf = 0; nf < 4; nf++) {
            int col = jt * 128 + wid * 32 + nf * 8 + 2 * tg;
            float2 s0 = *(const float2*)&attn[base0 + col];
            float2 s1 = *(const float2*)&attn[base1 + col];
            sc[jt][nf][0] += s0.x; sc[jt][nf][1] += s0.y;
            sc[jt][nf][2] += s1.x; sc[jt][nf][3] += s1.y;
            if (mks[col])     { sc[jt][nf][0] = -1e18f; sc[jt][nf][2] = -1e18f; }
            if (mks[col + 1]) { sc[jt][nf][1] = -1e18f; sc[jt][nf][3] = -1e18f; }
        }

    float mx0 = -1e30f, mx1 = -1e30f;
    #pragma unroll
    for (int jt = 0; jt < 4; jt++)
        #pragma unroll
        for (int nf = 0; nf < 4; nf++) {
            mx0 = fmaxf(mx0, fmaxf(sc[jt][nf][0], sc[jt][nf][1]));
            mx1 = fmaxf(mx1, fmaxf(sc[jt][nf][2], sc[jt][nf][3]));
        }
    #pragma unroll
    for (int o = 1; o <= 2; o <<= 1) {
        mx0 = fmaxf(mx0, __shfl_xor_sync(0xffffffffu, mx0, o));
        mx1 = fmaxf(mx1, __shfl_xor_sync(0xffffffffu, mx1, o));
    }
    if (tg == 0) { redmx[g * 4 + wid] = mx0; redmx[(g + 8) * 4 + wid] = mx1; }
    __syncthreads();
    mx0 = fmaxf(fmaxf(redmx[g * 4 + 0], redmx[g * 4 + 1]),
                fmaxf(redmx[g * 4 + 2], redmx[g * 4 + 3]));
    mx1 = fmaxf(fmaxf(redmx[(g + 8) * 4 + 0], redmx[(g + 8) * 4 + 1]),
                fmaxf(redmx[(g + 8) * 4 + 2], redmx[(g + 8) * 4 + 3]));

    float sm0 = 0.f, sm1 = 0.f;
    #pragma unroll
    for (int jt = 0; jt < 4; jt++)
        #pragma unroll
        for (int nf = 0; nf < 4; nf++) {
            sc[jt][nf][0] = __expf(sc[jt][nf][0] - mx0);
            sc[jt][nf][1] = __expf(sc[jt][nf][1] - mx0);
            sc[jt][nf][2] = __expf(sc[jt][nf][2] - mx1);
            sc[jt][nf][3] = __expf(sc[jt][nf][3] - mx1);
            sm0 += sc[jt][nf][0] + sc[jt][nf][1];
            sm1 += sc[jt][nf][2] + sc[jt][nf][3];
        }
    #pragma unroll
    for (int o = 1; o <= 2; o <<= 1) {
        sm0 += __shfl_xor_sync(0xffffffffu, sm0, o);
        sm1 += __shfl_xor_sync(0xffffffffu, sm1, o);
    }
    if (tg == 0) { redsm[g * 4 + wid] = sm0; redsm[(g + 8) * 4 + wid] = sm1; }
    __syncthreads();
    sm0 = redsm[g * 4 + 0] + redsm[g * 4 + 1] + redsm[g * 4 + 2] + redsm[g * 4 + 3];
    sm1 = redsm[(g + 8) * 4 + 0] + redsm[(g + 8) * 4 + 1] +
          redsm[(g + 8) * 4 + 2] + redsm[(g + 8) * 4 + 3];
    float inv0 = 1.0f / sm0, inv1 = 1.0f / sm1;

    #pragma unroll
    for (int jt = 0; jt < 4; jt++)
        #pragma unroll
        for (int nf = 0; nf < 4; nf++) {
            int col = jt * 128 + wid * 32 + nf * 8 + 2 * tg;
            *(float2*)&attn[base0 + col] =
                make_float2(sc[jt][nf][0] * inv0, sc[jt][nf][1] * inv0);
            *(float2*)&attn[base1 + col] =
                make_float2(sc[jt][nf][2] * inv1, sc[jt][nf][3] * inv1);
        }
}

// ---------------------------------------------------------------------------
// av: ctx[b][l][h*64+d] = sum_j attn[bh][l][j] * v[bh][j][d]
// Per bh: M=512 N=64 K=512. 128x64 tile, BK=16, 2-stage cp.async, static smem.
// A (attn) is raw fp32 -> cvt at fragment read; B (v) pre-rounded -> raw bits.
// ctx written tf32-rounded for the O-projection.
// ---------------------------------------------------------------------------
__global__ __launch_bounds__(256, 2) void av_tf32(const float* __restrict__ attn)
{
    __shared__ __align__(16) float    Asv[2][128 * AS_S];
    __shared__ __align__(16) unsigned Bsv[2][16 * BS64_S];

    const int NIT = 32;   // K=512 / 16

    int t = threadIdx.x;
    int bh = blockIdx.y;
    int m0 = blockIdx.x * 128;
    const float* __restrict__ A = attn + (size_t)bh * LL * LL;
    const float* __restrict__ V = g_v + bh * LL * DH;
    int wid = t >> 5, lane = t & 31;
    int wm = (wid >> 1) * 32, wn = (wid & 1) * 32;
    int g = lane >> 2, tg = lane & 3;

    int a_r = t >> 2, a_c = (t & 3) * 4;
    int b_r = t >> 4, b_c = (t & 15) * 4;

    const float* a_src = &A[(size_t)(m0 + a_r) * LL + a_c];
    const float* v_src = &V[b_r * DH + b_c];
    unsigned a_dst = smem_u32(&Asv[0][a_r * AS_S + a_c]);
    unsigned b_dst = smem_u32(&Bsv[0][b_r * BS64_S + b_c]);
    const unsigned a_stg = 128 * AS_S * 4;
    const unsigned b_stg = 16 * BS64_S * 4;

    float acc[2][4][4];
    #pragma unroll
    for (int i = 0; i < 2; i++)
        #pragma unroll
        for (int j = 0; j < 4; j++)
            #pragma unroll
            for (int e = 0; e < 4; e++) acc[i][j][e] = 0.f;

    cpa16(a_dst,                 a_src);
    cpa16(a_dst + 64 * AS_S * 4, a_src + 64 * LL);
    cpa16(b_dst,                 v_src);
    CP_COMMIT();

    for (int i = 0; i < NIT; i++) {
        CP_WAIT0();
        __syncthreads();

        int ki = i + 1;
        if (ki < NIT) {
            unsigned s = (unsigned)(ki & 1);
            cpa16(a_dst + s * a_stg,                 a_src + ki * 16);
            cpa16(a_dst + s * a_stg + 64 * AS_S * 4, a_src + ki * 16 + 64 * LL);
            cpa16(b_dst + s * b_stg,                 v_src + ki * 16 * DH);
            CP_COMMIT();
        }

        const float*    Ap = Asv[i & 1];
        const unsigned* Bp = Bsv[i & 1];

        #pragma unroll
        for (int kk = 0; kk < 16; kk += 8) {
            unsigned af[2][4], bf[4][2];
            #pragma unroll
            for (int mf = 0; mf < 2; mf++) {
                int row = wm + mf * 16 + g;
                af[mf][0] = f2tf(Ap[row * AS_S + kk + tg]);
                af[mf][1] = f2tf(Ap[(row + 8) * AS_S + kk + tg]);
                af[mf][2] = f2tf(Ap[row * AS_S + kk + 4 + tg]);
                af[mf][3] = f2tf(Ap[(row + 8) * AS_S + kk + 4 + tg]);
            }
            #pragma unroll
            for (int nf = 0; nf < 4; nf++) {
                int col = wn + nf * 8 + g;
                bf[nf][0] = Bp[(kk + tg) * BS64_S + col];
                bf[nf][1] = Bp[(kk + 4 + tg) * BS64_S + col];
            }
            #pragma unroll
            for (int mf = 0; mf < 2; mf++)
                #pragma unroll
                for (int nf = 0; nf < 4; nf++)
                    mma8(acc[mf][nf], af[mf], bf[nf], acc[mf][nf]);
        }
    }

    int b = bh >> 4, h = bh & 15;
    #pragma unroll
    for (int mf = 0; mf < 2; mf++)
        #pragma unroll
        for (int nf = 0; nf < 4; nf++) {
            int n = wn + nf * 8 + 2 * tg;
            #pragma unroll
            for (int rr = 0; rr < 2; rr++) {
                int l = m0 + wm + mf * 16 + g + rr * 8;
                float vx = __uint_as_float(f2tf(acc[mf][nf][rr * 2]));
                float vy = __uint_as_float(f2tf(acc[mf][nf][rr * 2 + 1]));
                *(float2*)&g_ctx[((b * LL + l) * DD) + h * DH + n] =
                    make_float2(vx, vy);
            }
        }
}

// ---------------------------------------------------------------------------
extern "C" void kernel_launch(void* const* d_in, const int* in_sizes, int n_in,
                              void* d_out, int out_size)
{
    const float* key   = (const float*)d_in[0];
    const float* value = (const float*)d_in[1];
    const float* query = (const float*)d_in[2];
    const int*   mat   = (const int*)d_in[3];
    const unsigned char* mask = (const unsigned char*)d_in[4];
    const float* Wq = (const float*)d_in[5];
    const float* bq = (const float*)d_in[6];
    const float* Wk = (const float*)d_in[7];
    const float* bk = (const float*)d_in[8];
    const float* Wv = (const float*)d_in[9];
    const float* bv = (const float*)d_in[10];
    const float* Wo = (const float*)d_in[11];
    const float* bo = (const float*)d_in[12];
    const float* semb = (const float*)d_in[13];
    const float* vemb = (const float*)d_in[14];

    float* out  = (float*)d_out;
    float* attn = out + OUT_ELEMS;   // scores buffer, finalized in astsm

    float *q, *k, *v, *ctx;
    cudaGetSymbolAddress((void**)&q,   g_q);
    cudaGetSymbolAddress((void**)&k,   g_k);
    cudaGetSymbolAddress((void**)&v,   g_v);
    cudaGetSymbolAddress((void**)&ctx, g_ctx);

    // Merged Q/K/V projection: one launch, 384 blocks
    PArgs qkv;
    qkv.p[0] = { query, Wq, bq, q, 0.125f, 1 };
    qkv.p[1] = { key,   Wk, bk, k, 1.0f,   2 };
    qkv.p[2] = { value, Wv, bv, v, 1.0f,   1 };
    proj_tf32<<<dim3(8, 16, 3), 256>>>(qkv);

    qk_tf32<<<dim3(4, 4, BH), 256>>>(attn);
    astsm_tf32<<<dim3(LL, BB), 128>>>(mat, semb, vemb, attn, mask);
    av_tf32<<<dim3(4, BH), 256>>>(attn);

    PArgs oarg;
    oarg.p[0] = { ctx, Wo, bo, out, 1.0f, 0 };
    oarg.p[1] = oarg.p[0];
    oarg.p[2] = oarg.p[0];
    proj_tf32<<<dim3(8, 16, 1), 256>>>(oarg);
}

// round 12
// speedup vs baseline: 1.0213x; 1.0213x over previous
#include <cuda_runtime.h>

// Problem constants
#define BB 4
#define LL 512
#define DD 1024
#define HH 16
#define DH 64
#define BH (BB*HH)            // 64
#define OUT_ELEMS (BB*LL*DD)  // 2097152

// Scratch (no allocations allowed -> __device__ globals)
// Values stored tf32-rounded (bit patterns of cvt.rna.tf32) so consumers can
// feed smem bits directly to mma without per-fragment cvt.
__device__ float g_q[BB*HH*LL*DH];    // [b][h][l][dh]   (rounded)
__device__ float g_k[BB*HH*LL*DH];    // [b][h][dh][l]   (rounded, transposed)
__device__ float g_v[BB*HH*LL*DH];    // [b][h][l][dh]   (rounded)
__device__ float g_ctx[BB*LL*DD];     // (rounded)

// ---------------------------------------------------------------------------
// tf32 helpers (mma.sync m16n8k8, row.col, f32 accum)
// ---------------------------------------------------------------------------
__device__ __forceinline__ unsigned f2tf(float x) {
    unsigned y; asm("cvt.rna.tf32.f32 %0, %1;" : "=r"(y) : "f"(x)); return y;
}
__device__ __forceinline__ uint4 cvt4(float4 v) {
    uint4 u; u.x = f2tf(v.x); u.y = f2tf(v.y); u.z = f2tf(v.z); u.w = f2tf(v.w);
    return u;
}
__device__ __forceinline__ void mma8(float* d, const unsigned* a,
                                     const unsigned* b, const float* c) {
    asm volatile(
        "mma.sync.aligned.m16n8k8.row.col.f32.tf32.tf32.f32 "
        "{%0,%1,%2,%3}, {%4,%5,%6,%7}, {%8,%9}, {%10,%11,%12,%13};"
        : "=f"(d[0]), "=f"(d[1]), "=f"(d[2]), "=f"(d[3])
        : "r"(a[0]), "r"(a[1]), "r"(a[2]), "r"(a[3]),
          "r"(b[0]), "r"(b[1]),
          "f"(c[0]), "f"(c[1]), "f"(c[2]), "f"(c[3]));
}

__device__ __forceinline__ unsigned smem_u32(const void* p) {
    return (unsigned)__cvta_generic_to_shared(p);
}
__device__ __forceinline__ void cpa16(unsigned dst, const void* src) {
    asm volatile("cp.async.cg.shared.global [%0], [%1], 16;" :: "r"(dst), "l"(src));
}
#define CP_COMMIT() asm volatile("cp.async.commit_group;")
#define CP_WAIT0()  asm volatile("cp.async.wait_group 0;")

// Smem strides (elements), conflict-free fragment reads:
//   As stride 20, Bs stride 136, Bs64 stride 72 (banks all-distinct per warp)
#define AS_S 20
#define BS_S 136
#define BS64_S 72

struct PArg { const float* A; const float* W; const float* bias;
              float* out; float scale; int mode; };
struct PArgs { PArg p[3]; };

// ---------------------------------------------------------------------------
// Projection GEMM: C = A(2048x1024) @ W(1024x1024) + bias, scale.
// mode 0: out[m][n] raw; mode 1: [b][h][l][dh] rounded; mode 2: [b][h][dh][l].
// 64x128 tile, BK=16, 128 threads (4 warps, 2m x 2n, warp tile 32x64),
// 2-stage cp.async, STATIC smem (27.6KB) -> 4+ blocks/SM.
// ---------------------------------------------------------------------------
__global__ __launch_bounds__(128, 4) void proj_tf32(PArgs args)
{
    __shared__ __align__(16) float Asf[2][64 * AS_S];
    __shared__ __align__(16) float Bsf[2][16 * BS_S];

    const int K = 1024, N = 1024, NIT = 64;

    PArg pa = args.p[blockIdx.z];
    const float* __restrict__ A = pa.A;
    const float* __restrict__ W = pa.W;

    int t = threadIdx.x;
    int m0 = blockIdx.y * 64, n0 = blockIdx.x * 128;
    int wid = t >> 5, lane = t & 31;
    int wm = (wid >> 1) * 32, wn = (wid & 1) * 64;
    int g = lane >> 2, tg = lane & 3;

    int a_r = t >> 2;            // 0..31 (+32)
    int a_c = (t & 3) * 4;
    int b_r = t >> 5;            // 0..3 (+4,+8,+12)
    int b_c = (t & 31) * 4;

    const float* a_src = &A[(m0 + a_r) * K + a_c];
    const float* w_src = &W[b_r * N + n0 + b_c];
    unsigned a_dst = smem_u32(&Asf[0][a_r * AS_S + a_c]);
    unsigned b_dst = smem_u32(&Bsf[0][b_r * BS_S + b_c]);
    const unsigned a_stg = 64 * AS_S * 4;
    const unsigned b_stg = 16 * BS_S * 4;

    float acc[2][8][4];
    #pragma unroll
    for (int i = 0; i < 2; i++)
        #pragma unroll
        for (int j = 0; j < 8; j++)
            #pragma unroll
            for (int e = 0; e < 4; e++) acc[i][j][e] = 0.f;

    // tile 0 -> stage 0
    cpa16(a_dst,                  a_src);
    cpa16(a_dst + 32 * AS_S * 4,  a_src + 32 * K);
    cpa16(b_dst,                  w_src);
    cpa16(b_dst + 4 * BS_S * 4,   w_src + 4 * N);
    cpa16(b_dst + 8 * BS_S * 4,   w_src + 8 * N);
    cpa16(b_dst + 12 * BS_S * 4,  w_src + 12 * N);
    CP_COMMIT();

    for (int i = 0; i < NIT; i++) {
        CP_WAIT0();
        __syncthreads();

        int ki = i + 1;
        if (ki < NIT) {
            unsigned s = (unsigned)(ki & 1);
            const float* as = a_src + ki * 16;
            const float* ws = w_src + ki * 16 * N;
            cpa16(a_dst + s * a_stg,                 as);
            cpa16(a_dst + s * a_stg + 32 * AS_S * 4, as + 32 * K);
            cpa16(b_dst + s * b_stg,                 ws);
            cpa16(b_dst + s * b_stg + 4 * BS_S * 4,  ws + 4 * N);
            cpa16(b_dst + s * b_stg + 8 * BS_S * 4,  ws + 8 * N);
            cpa16(b_dst + s * b_stg + 12 * BS_S * 4, ws + 12 * N);
            CP_COMMIT();
        }

        const float* Ap = Asf[i & 1];
        const float* Bp = Bsf[i & 1];

        #pragma unroll
        for (int kk = 0; kk < 16; kk += 8) {
            unsigned af[2][4], bf[8][2];
            #pragma unroll
            for (int mf = 0; mf < 2; mf++) {
                int row = wm + mf * 16 + g;
                af[mf][0] = f2tf(Ap[row * AS_S + kk + tg]);
                af[mf][1] = f2tf(Ap[(row + 8) * AS_S + kk + tg]);
                af[mf][2] = f2tf(Ap[row * AS_S + kk + 4 + tg]);
                af[mf][3] = f2tf(Ap[(row + 8) * AS_S + kk + 4 + tg]);
            }
            #pragma unroll
            for (int nf = 0; nf < 8; nf++) {
                int col = wn + nf * 8 + g;
                bf[nf][0] = f2tf(Bp[(kk + tg) * BS_S + col]);
                bf[nf][1] = f2tf(Bp[(kk + 4 + tg) * BS_S + col]);
            }
            #pragma unroll
            for (int mf = 0; mf < 2; mf++)
                #pragma unroll
                for (int nf = 0; nf < 8; nf++)
                    mma8(acc[mf][nf], af[mf], bf[nf], acc[mf][nf]);
        }
    }

    #pragma unroll
    for (int mf = 0; mf < 2; mf++) {
        #pragma unroll
        for (int nf = 0; nf < 8; nf++) {
            int col = n0 + wn + nf * 8 + 2 * tg;
            float2 b2 = *(const float2*)&pa.bias[col];
            #pragma unroll
            for (int rr = 0; rr < 2; rr++) {
                int m = m0 + wm + mf * 16 + g + rr * 8;
                float vx = (acc[mf][nf][rr * 2 + 0] + b2.x) * pa.scale;
                float vy = (acc[mf][nf][rr * 2 + 1] + b2.y) * pa.scale;
                if (pa.mode == 0) {
                    *(float2*)&pa.out[m * 1024 + col] = make_float2(vx, vy);
                } else {
                    vx = __uint_as_float(f2tf(vx));
                    vy = __uint_as_float(f2tf(vy));
                    int b = m >> 9, l = m & 511;
                    int h = col >> 6, dh = col & 63;
                    if (pa.mode == 1) {
                        *(float2*)&pa.out[((b * HH + h) * LL + l) * DH + dh] =
                            make_float2(vx, vy);
                    } else {
                        pa.out[((b * HH + h) * DH + dh) * LL + l] = vx;
                        pa.out[((b * HH + h) * DH + dh + 1) * LL + l] = vy;
                    }
                }
            }
        }
    }
}

// ---------------------------------------------------------------------------
// qk: scores[bh][i][j] = q[bh][i][:] . kT[bh][:][j]  (M=N=512, K=64 per bh)
// 64x128 tile, 128 threads, 2-stage cp.async. Operands pre-rounded -> raw bits.
// ---------------------------------------------------------------------------
__global__ __launch_bounds__(128, 4) void qk_tf32(float* __restrict__ scores)
{
    __shared__ __align__(16) unsigned Asq[2][64 * AS_S];
    __shared__ __align__(16) unsigned Bsq[2][16 * BS_S];

    const int NIT = 4;   // K=64 / 16

    int t = threadIdx.x;
    int bh = blockIdx.z;
    const float* __restrict__ Q  = g_q + bh * LL * DH;   // [l][dh]
    const float* __restrict__ KT = g_k + bh * LL * DH;   // [dh][l]
    int m0 = blockIdx.y * 64, n0 = blockIdx.x * 128;
    int wid = t >> 5, lane = t & 31;
    int wm = (wid >> 1) * 32, wn = (wid & 1) * 64;
    int g = lane >> 2, tg = lane & 3;

    int a_r = t >> 2, a_c = (t & 3) * 4;
    int b_r = t >> 5, b_c = (t & 31) * 4;

    const float* a_src = &Q[(m0 + a_r) * DH + a_c];
    const float* k_src = &KT[b_r * LL + n0 + b_c];
    unsigned a_dst = smem_u32(&Asq[0][a_r * AS_S + a_c]);
    unsigned b_dst = smem_u32(&Bsq[0][b_r * BS_S + b_c]);
    const unsigned a_stg = 64 * AS_S * 4;
    const unsigned b_stg = 16 * BS_S * 4;

    float acc[2][8][4];
    #pragma unroll
    for (int i = 0; i < 2; i++)
        #pragma unroll
        for (int j = 0; j < 8; j++)
            #pragma unroll
            for (int e = 0; e < 4; e++) acc[i][j][e] = 0.f;

    cpa16(a_dst,                 a_src);
    cpa16(a_dst + 32 * AS_S * 4, a_src + 32 * DH);
    cpa16(b_dst,                 k_src);
    cpa16(b_dst + 4 * BS_S * 4,  k_src + 4 * LL);
    cpa16(b_dst + 8 * BS_S * 4,  k_src + 8 * LL);
    cpa16(b_dst + 12 * BS_S * 4, k_src + 12 * LL);
    CP_COMMIT();

    for (int i = 0; i < NIT; i++) {
        CP_WAIT0();
        __syncthreads();

        int ki = i + 1;
        if (ki < NIT) {
            unsigned s = (unsigned)(ki & 1);
            const float* as = a_src + ki * 16;
            const float* ks = k_src + ki * 16 * LL;
            cpa16(a_dst + s * a_stg,                 as);
            cpa16(a_dst + s * a_stg + 32 * AS_S * 4, as + 32 * DH);
            cpa16(b_dst + s * b_stg,                 ks);
            cpa16(b_dst + s * b_stg + 4 * BS_S * 4,  ks + 4 * LL);
            cpa16(b_dst + s * b_stg + 8 * BS_S * 4,  ks + 8 * LL);
            cpa16(b_dst + s * b_stg + 12 * BS_S * 4, ks + 12 * LL);
            CP_COMMIT();
        }

        const unsigned* Ap = Asq[i & 1];
        const unsigned* Bp = Bsq[i & 1];

        #pragma unroll
        for (int kk = 0; kk < 16; kk += 8) {
            unsigned af[2][4], bf[8][2];
            #pragma unroll
            for (int mf = 0; mf < 2; mf++) {
                int row = wm + mf * 16 + g;
                af[mf][0] = Ap[row * AS_S + kk + tg];
                af[mf][1] = Ap[(row + 8) * AS_S + kk + tg];
                af[mf][2] = Ap[row * AS_S + kk + 4 + tg];
                af[mf][3] = Ap[(row + 8) * AS_S + kk + 4 + tg];
            }
            #pragma unroll
            for (int nf = 0; nf < 8; nf++) {
                int col = wn + nf * 8 + g;
                bf[nf][0] = Bp[(kk + tg) * BS_S + col];
                bf[nf][1] = Bp[(kk + 4 + tg) * BS_S + col];
            }
            #pragma unroll
            for (int mf = 0; mf < 2; mf++)
                #pragma unroll
                for (int nf = 0; nf < 8; nf++)
                    mma8(acc[mf][nf], af[mf], bf[nf], acc[mf][nf]);
        }
    }

    float* srow = scores + (size_t)bh * LL * LL;
    #pragma unroll
    for (int mf = 0; mf < 2; mf++)
        #pragma unroll
        for (int nf = 0; nf < 8; nf++) {
            int col = n0 + wn + nf * 8 + 2 * tg;
            #pragma unroll
            for (int rr = 0; rr < 2; rr++) {
                int m = m0 + wm + mf * 16 + g + rr * 8;
                *(float2*)&srow[m * LL + col] =
                    make_float2(acc[mf][nf][rr * 2], acc[mf][nf][rr * 2 + 1]);
            }
        }
}

// ---------------------------------------------------------------------------
// Fused ast + mask + softmax. Block (i, b), 128 threads.  (unchanged, proven)
// ---------------------------------------------------------------------------
__global__ __launch_bounds__(128) void astsm_tf32(
    const int* __restrict__ mat, const float* __restrict__ semb,
    const float* __restrict__ vemb, float* __restrict__ attn,
    const unsigned char* __restrict__ mask)
{
    __shared__ __align__(16) unsigned qs[16 * 68];
    __shared__ __align__(16) unsigned pe[128 * 68];
    __shared__ unsigned char mks[512];
    __shared__ float redmx[16 * 4];
    __shared__ float redsm[16 * 4];

    int i = blockIdx.x, b = blockIdx.y;
    int t = threadIdx.x;
    int wid = t >> 5, lane = t & 31;
    int g = lane >> 2, tg = lane & 3;

    for (int idx = t; idx < HH * DH; idx += 128) {
        int h = idx >> 6, d = idx & 63;
        qs[h * 68 + d] = f2tf(g_q[((b * HH + h) * LL + i) * DH + d]);
    }
    *(uchar4*)&mks[t * 4] = *(const uchar4*)&mask[b * LL + t * 4];
    __syncthreads();

    unsigned af[8][4];
    #pragma unroll
    for (int ks = 0; ks < 8; ks++) {
        af[ks][0] = qs[g * 68 + ks * 8 + tg];
        af[ks][1] = qs[(g + 8) * 68 + ks * 8 + tg];
        af[ks][2] = qs[g * 68 + ks * 8 + 4 + tg];
        af[ks][3] = qs[(g + 8) * 68 + ks * 8 + 4 + tg];
    }

    const int* mrow = mat + (b * LL + i) * LL;
    float sc[4][4][4];   // [jt][nf][e]

    for (int jt = 0; jt < 4; jt++) {
        int j0 = jt * 128;
        __syncthreads();
        {
            int j = j0 + t;
            int id = mrow[j];
            const float* e = ((j & 1) ? vemb : semb) + id * DH;
            #pragma unroll
            for (int s = 0; s < 64; s += 4)
                *(uint4*)&pe[t * 68 + s] = cvt4(*(const float4*)&e[s]);
        }
        __syncthreads();

        #pragma unroll
        for (int nf = 0; nf < 4; nf++)
            #pragma unroll
            for (int e = 0; e < 4; e++) sc[jt][nf][e] = 0.f;

        #pragma unroll
        for (int ks = 0; ks < 8; ks++) {
            #pragma unroll
            for (int nf = 0; nf < 4; nf++) {
                int jj = wid * 32 + nf * 8 + g;
                unsigned bf[2];
                bf[0] = pe[jj * 68 + ks * 8 + tg];
                bf[1] = pe[jj * 68 + ks * 8 + 4 + tg];
                mma8(sc[jt][nf], af[ks], bf, sc[jt][nf]);
            }
        }
    }

    size_t base0 = (((size_t)(b * HH + g) * LL + i) * LL);
    size_t base1 = (((size_t)(b * HH + g + 8) * LL + i) * LL);
    #pragma unroll
    for (int jt = 0; jt < 4; jt++)
        #pragma unroll
        for (int nf = 0; nf < 4; nf++) {
            int col = jt * 128 + wid * 32 + nf * 8 + 2 * tg;
            float2 s0 = *(const float2*)&attn[base0 + col];
            float2 s1 = *(const float2*)&attn[base1 + col];
            sc[jt][nf][0] += s0.x; sc[jt][nf][1] += s0.y;
            sc[jt][nf][2] += s1.x; sc[jt][nf][3] += s1.y;
            if (mks[col])     { sc[jt][nf][0] = -1e18f; sc[jt][nf][2] = -1e18f; }
            if (mks[col + 1]) { sc[jt][nf][1] = -1e18f; sc[jt][nf][3] = -1e18f; }
        }

    float mx0 = -1e30f, mx1 = -1e30f;
    #pragma unroll
    for (int jt = 0; jt < 4; jt++)
        #pragma unroll
        for (int nf = 0; nf < 4; nf++) {
            mx0 = fmaxf(mx0, fmaxf(sc[jt][nf][0], sc[jt][nf][1]));
            mx1 = fmaxf(mx1, fmaxf(sc[jt][nf][2], sc[jt][nf][3]));
        }
    #pragma unroll
    for (int o = 1; o <= 2; o <<= 1) {
        mx0 = fmaxf(mx0, __shfl_xor_sync(0xffffffffu, mx0, o));
        mx1 = fmaxf(mx1, __shfl_xor_sync(0xffffffffu, mx1, o));
    }
    if (tg == 0) { redmx[g * 4 + wid] = mx0; redmx[(g + 8) * 4 + wid] = mx1; }
    __syncthreads();
    mx0 = fmaxf(fmaxf(redmx[g * 4 + 0], redmx[g * 4 + 1]),
                fmaxf(redmx[g * 4 + 2], redmx[g * 4 + 3]));
    mx1 = fmaxf(fmaxf(redmx[(g + 8) * 4 + 0], redmx[(g + 8) * 4 + 1]),
                fmaxf(redmx[(g + 8) * 4 + 2], redmx[(g + 8) * 4 + 3]));

    float sm0 = 0.f, sm1 = 0.f;
    #pragma unroll
    for (int jt = 0; jt < 4; jt++)
        #pragma unroll
        for (int nf = 0; nf < 4; nf++) {
            sc[jt][nf][0] = __expf(sc[jt][nf][0] - mx0);
            sc[jt][nf][1] = __expf(sc[jt][nf][1] - mx0);
            sc[jt][nf][2] = __expf(sc[jt][nf][2] - mx1);
            sc[jt][nf][3] = __expf(sc[jt][nf][3] - mx1);
            sm0 += sc[jt][nf][0] + sc[jt][nf][1];
            sm1 += sc[jt][nf][2] + sc[jt][nf][3];
        }
    #pragma unroll
    for (int o = 1; o <= 2; o <<= 1) {
        sm0 += __shfl_xor_sync(0xffffffffu, sm0, o);
        sm1 += __shfl_xor_sync(0xffffffffu, sm1, o);
    }
    if (tg == 0) { redsm[g * 4 + wid] = sm0; redsm[(g + 8) * 4 + wid] = sm1; }
    __syncthreads();
    sm0 = redsm[g * 4 + 0] + redsm[g * 4 + 1] + redsm[g * 4 + 2] + redsm[g * 4 + 3];
    sm1 = redsm[(g + 8) * 4 + 0] + redsm[(g + 8) * 4 + 1] +
          redsm[(g + 8) * 4 + 2] + redsm[(g + 8) * 4 + 3];
    float inv0 = 1.0f / sm0, inv1 = 1.0f / sm1;

    #pragma unroll
    for (int jt = 0; jt < 4; jt++)
        #pragma unroll
        for (int nf = 0; nf < 4; nf++) {
            int col = jt * 128 + wid * 32 + nf * 8 + 2 * tg;
            *(float2*)&attn[base0 + col] =
                make_float2(sc[jt][nf][0] * inv0, sc[jt][nf][1] * inv0);
            *(float2*)&attn[base1 + col] =
                make_float2(sc[jt][nf][2] * inv1, sc[jt][nf][3] * inv1);
        }
}

// ---------------------------------------------------------------------------
// av: ctx[b][l][h*64+d] = sum_j attn[bh][l][j] * v[bh][j][d]
// Per bh: M=512 N=64 K=512. 64x64 tile, 128 threads (4 warps, 2m x 2n,
// warp tile 32x32), BK=16, 2-stage cp.async (19.5KB smem).
// ---------------------------------------------------------------------------
__global__ __launch_bounds__(128, 4) void av_tf32(const float* __restrict__ attn)
{
    __shared__ __align__(16) float    Asv[2][64 * AS_S];
    __shared__ __align__(16) unsigned Bsv[2][16 * BS64_S];

    const int NIT = 32;   // K=512 / 16

    int t = threadIdx.x;
    int bh = blockIdx.y;
    int m0 = blockIdx.x * 64;
    const float* __restrict__ A = attn + (size_t)bh * LL * LL;
    const float* __restrict__ V = g_v + bh * LL * DH;
    int wid = t >> 5, lane = t & 31;
    int wm = (wid >> 1) * 32, wn = (wid & 1) * 32;
    int g = lane >> 2, tg = lane & 3;

    int a_r = t >> 2, a_c = (t & 3) * 4;   // 0..31 (+32)
    int b_r = t >> 4, b_c = (t & 15) * 4;  // 0..7 (+8)

    const float* a_src = &A[(size_t)(m0 + a_r) * LL + a_c];
    const float* v_src = &V[b_r * DH + b_c];
    unsigned a_dst = smem_u32(&Asv[0][a_r * AS_S + a_c]);
    unsigned b_dst = smem_u32(&Bsv[0][b_r * BS64_S + b_c]);
    const unsigned a_stg = 64 * AS_S * 4;
    const unsigned b_stg = 16 * BS64_S * 4;

    float acc[2][4][4];
    #pragma unroll
    for (int i = 0; i < 2; i++)
        #pragma unroll
        for (int j = 0; j < 4; j++)
            #pragma unroll
            for (int e = 0; e < 4; e++) acc[i][j][e] = 0.f;

    cpa16(a_dst,                 a_src);
    cpa16(a_dst + 32 * AS_S * 4, a_src + 32 * LL);
    cpa16(b_dst,                 v_src);
    cpa16(b_dst + 8 * BS64_S * 4, v_src + 8 * DH);
    CP_COMMIT();

    for (int i = 0; i < NIT; i++) {
        CP_WAIT0();
        __syncthreads();

        int ki = i + 1;
        if (ki < NIT) {
            unsigned s = (unsigned)(ki & 1);
            const float* as = a_src + ki * 16;
            const float* vs = v_src + ki * 16 * DH;
            cpa16(a_dst + s * a_stg,                 as);
            cpa16(a_dst + s * a_stg + 32 * AS_S * 4, as + 32 * LL);
            cpa16(b_dst + s * b_stg,                 vs);
            cpa16(b_dst + s * b_stg + 8 * BS64_S * 4, vs + 8 * DH);
            CP_COMMIT();
        }

        const float*    Ap = Asv[i & 1];
        const unsigned* Bp = Bsv[i & 1];

        #pragma unroll
        for (int kk = 0; kk < 16; kk += 8) {
            unsigned af[2][4], bf[4][2];
            #pragma unroll
            for (int mf = 0; mf < 2; mf++) {
                int row = wm + mf * 16 + g;
                af[mf][0] = f2tf(Ap[row * AS_S + kk + tg]);
                af[mf][1] = f2tf(Ap[(row + 8) * AS_S + kk + tg]);
                af[mf][2] = f2tf(Ap[row * AS_S + kk + 4 + tg]);
                af[mf][3] = f2tf(Ap[(row + 8) * AS_S + kk + 4 + tg]);
            }
            #pragma unroll
            for (int nf = 0; nf < 4; nf++) {
                int col = wn + nf * 8 + g;
                bf[nf][0] = Bp[(kk + tg) * BS64_S + col];
                bf[nf][1] = Bp[(kk + 4 + tg) * BS64_S + col];
            }
            #pragma unroll
            for (int mf = 0; mf < 2; mf++)
                #pragma unroll
                for (int nf = 0; nf < 4; nf++)
                    mma8(acc[mf][nf], af[mf], bf[nf], acc[mf][nf]);
        }
    }

    int b = bh >> 4, h = bh & 15;
    #pragma unroll
    for (int mf = 0; mf < 2; mf++)
        #pragma unroll
        for (int nf = 0; nf < 4; nf++) {
            int n = wn + nf * 8 + 2 * tg;
            #pragma unroll
            for (int rr = 0; rr < 2; rr++) {
                int l = m0 + wm + mf * 16 + g + rr * 8;
                float vx = __uint_as_float(f2tf(acc[mf][nf][rr * 2]));
                float vy = __uint_as_float(f2tf(acc[mf][nf][rr * 2 + 1]));
                *(float2*)&g_ctx[((b * LL + l) * DD) + h * DH + n] =
                    make_float2(vx, vy);
            }
        }
}

// ---------------------------------------------------------------------------
extern "C" void kernel_launch(void* const* d_in, const int* in_sizes, int n_in,
                              void* d_out, int out_size)
{
    const float* key   = (const float*)d_in[0];
    const float* value = (const float*)d_in[1];
    const float* query = (const float*)d_in[2];
    const int*   mat   = (const int*)d_in[3];
    const unsigned char* mask = (const unsigned char*)d_in[4];
    const float* Wq = (const float*)d_in[5];
    const float* bq = (const float*)d_in[6];
    const float* Wk = (const float*)d_in[7];
    const float* bk = (const float*)d_in[8];
    const float* Wv = (const float*)d_in[9];
    const float* bv = (const float*)d_in[10];
    const float* Wo = (const float*)d_in[11];
    const float* bo = (const float*)d_in[12];
    const float* semb = (const float*)d_in[13];
    const float* vemb = (const float*)d_in[14];

    float* out  = (float*)d_out;
    float* attn = out + OUT_ELEMS;   // scores buffer, finalized in astsm

    float *q, *k, *v, *ctx;
    cudaGetSymbolAddress((void**)&q,   g_q);
    cudaGetSymbolAddress((void**)&k,   g_k);
    cudaGetSymbolAddress((void**)&v,   g_v);
    cudaGetSymbolAddress((void**)&ctx, g_ctx);

    // Merged Q/K/V projection: one launch, 768 blocks
    PArgs qkv;
    qkv.p[0] = { query, Wq, bq, q, 0.125f, 1 };
    qkv.p[1] = { key,   Wk, bk, k, 1.0f,   2 };
    qkv.p[2] = { value, Wv, bv, v, 1.0f,   1 };
    proj_tf32<<<dim3(8, 32, 3), 128>>>(qkv);

    qk_tf32<<<dim3(4, 8, BH), 128>>>(attn);
    astsm_tf32<<<dim3(LL, BB), 128>>>(mat, semb, vemb, attn, mask);
    av_tf32<<<dim3(8, BH), 128>>>(attn);

    PArgs oarg;
    oarg.p[0] = { ctx, Wo, bo, out, 1.0f, 0 };
    oarg.p[1] = oarg.p[0];
    oarg.p[2] = oarg.p[0];
    proj_tf32<<<dim3(8, 32, 1), 128>>>(oarg);
}

// round 13
// speedup vs baseline: 1.0749x; 1.0524x over previous
#include <cuda_runtime.h>

// Problem constants
#define BB 4
#define LL 512
#define DD 1024
#define HH 16
#define DH 64
#define BH (BB*HH)            // 64
#define OUT_ELEMS (BB*LL*DD)  // 2097152

// Scratch (no allocations allowed -> __device__ globals)
// Values stored tf32-rounded (bit patterns of cvt.rna.tf32) so consumers can
// feed smem bits directly to mma without per-fragment cvt.
__device__ float g_q[BB*HH*LL*DH];    // [b][h][l][dh]   (rounded)
__device__ float g_k[BB*HH*LL*DH];    // [b][h][dh][l]   (rounded, transposed)
__device__ float g_v[BB*HH*LL*DH];    // [b][h][l][dh]   (rounded)
__device__ float g_ctx[BB*LL*DD];     // (rounded)

// ---------------------------------------------------------------------------
// tf32 helpers (mma.sync m16n8k8, row.col, f32 accum)
// ---------------------------------------------------------------------------
__device__ __forceinline__ unsigned f2tf(float x) {
    unsigned y; asm("cvt.rna.tf32.f32 %0, %1;" : "=r"(y) : "f"(x)); return y;
}
__device__ __forceinline__ uint4 cvt4(float4 v) {
    uint4 u; u.x = f2tf(v.x); u.y = f2tf(v.y); u.z = f2tf(v.z); u.w = f2tf(v.w);
    return u;
}
__device__ __forceinline__ void mma8(float* d, const unsigned* a,
                                     const unsigned* b, const float* c) {
    asm volatile(
        "mma.sync.aligned.m16n8k8.row.col.f32.tf32.tf32.f32 "
        "{%0,%1,%2,%3}, {%4,%5,%6,%7}, {%8,%9}, {%10,%11,%12,%13};"
        : "=f"(d[0]), "=f"(d[1]), "=f"(d[2]), "=f"(d[3])
        : "r"(a[0]), "r"(a[1]), "r"(a[2]), "r"(a[3]),
          "r"(b[0]), "r"(b[1]),
          "f"(c[0]), "f"(c[1]), "f"(c[2]), "f"(c[3]));
}

__device__ __forceinline__ unsigned smem_u32(const void* p) {
    return (unsigned)__cvta_generic_to_shared(p);
}
__device__ __forceinline__ void cpa16(unsigned dst, const void* src) {
    asm volatile("cp.async.cg.shared.global [%0], [%1], 16;" :: "r"(dst), "l"(src));
}
#define CP_COMMIT() asm volatile("cp.async.commit_group;")
#define CP_WAIT1()  asm volatile("cp.async.wait_group 1;")

// Smem strides (elements), conflict-free fragment reads:
//   As stride 20, Bs stride 136, Bs64 stride 72 (banks all-distinct per warp)
#define AS_S 20
#define BS_S 136
#define BS64_S 72
#define NSTG 3

struct PArg { const float* A; const float* W; const float* bias;
              float* out; float scale; int mode; };
struct PArgs { PArg p[3]; };

// ---------------------------------------------------------------------------
// Projection GEMM: C = A(2048x1024) @ W(1024x1024) + bias, scale.
// mode 0: out[m][n] raw; mode 1: [b][h][l][dh] rounded; mode 2: [b][h][dh][l].
// 64x128 tile, BK=16, 128 threads (4 warps, 2m x 2n, warp tile 32x64),
// 3-stage cp.async pipeline (wait_group 1), static smem 41.5KB.
// ---------------------------------------------------------------------------
__global__ __launch_bounds__(128, 4) void proj_tf32(PArgs args)
{
    __shared__ __align__(16) float Asf[NSTG][64 * AS_S];
    __shared__ __align__(16) float Bsf[NSTG][16 * BS_S];

    const int K = 1024, N = 1024, NIT = 64;

    PArg pa = args.p[blockIdx.z];
    const float* __restrict__ A = pa.A;
    const float* __restrict__ W = pa.W;

    int t = threadIdx.x;
    int m0 = blockIdx.y * 64, n0 = blockIdx.x * 128;
    int wid = t >> 5, lane = t & 31;
    int wm = (wid >> 1) * 32, wn = (wid & 1) * 64;
    int g = lane >> 2, tg = lane & 3;

    int a_r = t >> 2;            // 0..31 (+32)
    int a_c = (t & 3) * 4;
    int b_r = t >> 5;            // 0..3 (+4,+8,+12)
    int b_c = (t & 31) * 4;

    const float* a_src = &A[(m0 + a_r) * K + a_c];
    const float* w_src = &W[b_r * N + n0 + b_c];
    unsigned a_dst = smem_u32(&Asf[0][a_r * AS_S + a_c]);
    unsigned b_dst = smem_u32(&Bsf[0][b_r * BS_S + b_c]);
    const unsigned a_stg = 64 * AS_S * 4;
    const unsigned b_stg = 16 * BS_S * 4;

    float acc[2][8][4];
    #pragma unroll
    for (int i = 0; i < 2; i++)
        #pragma unroll
        for (int j = 0; j < 8; j++)
            #pragma unroll
            for (int e = 0; e < 4; e++) acc[i][j][e] = 0.f;

    // prologue: tiles 0,1 -> stages 0,1 (two groups in flight)
    #pragma unroll
    for (int s = 0; s < 2; s++) {
        const float* as = a_src + s * 16;
        const float* ws = w_src + s * 16 * N;
        cpa16(a_dst + s * a_stg,                 as);
        cpa16(a_dst + s * a_stg + 32 * AS_S * 4, as + 32 * K);
        cpa16(b_dst + s * b_stg,                 ws);
        cpa16(b_dst + s * b_stg + 4 * BS_S * 4,  ws + 4 * N);
        cpa16(b_dst + s * b_stg + 8 * BS_S * 4,  ws + 8 * N);
        cpa16(b_dst + s * b_stg + 12 * BS_S * 4, ws + 12 * N);
        CP_COMMIT();
    }

    for (int i = 0; i < NIT; i++) {
        CP_WAIT1();          // stage i arrived (exactly 2 groups pending before)
        __syncthreads();     // ...and stage (i+2)%3 free of readers

        int ki = i + 2;
        if (ki < NIT) {
            unsigned s = (unsigned)(ki % 3);
            const float* as = a_src + ki * 16;
            const float* ws = w_src + ki * 16 * N;
            cpa16(a_dst + s * a_stg,                 as);
            cpa16(a_dst + s * a_stg + 32 * AS_S * 4, as + 32 * K);
            cpa16(b_dst + s * b_stg,                 ws);
            cpa16(b_dst + s * b_stg + 4 * BS_S * 4,  ws + 4 * N);
            cpa16(b_dst + s * b_stg + 8 * BS_S * 4,  ws + 8 * N);
            cpa16(b_dst + s * b_stg + 12 * BS_S * 4, ws + 12 * N);
        }
        CP_COMMIT();         // unconditional: keeps pending-group count = 2

        const float* Ap = Asf[i % 3];
        const float* Bp = Bsf[i % 3];

        #pragma unroll
        for (int kk = 0; kk < 16; kk += 8) {
            unsigned af[2][4], bf[8][2];
            #pragma unroll
            for (int mf = 0; mf < 2; mf++) {
                int row = wm + mf * 16 + g;
                af[mf][0] = f2tf(Ap[row * AS_S + kk + tg]);
                af[mf][1] = f2tf(Ap[(row + 8) * AS_S + kk + tg]);
                af[mf][2] = f2tf(Ap[row * AS_S + kk + 4 + tg]);
                af[mf][3] = f2tf(Ap[(row + 8) * AS_S + kk + 4 + tg]);
            }
            #pragma unroll
            for (int nf = 0; nf < 8; nf++) {
                int col = wn + nf * 8 + g;
                bf[nf][0] = f2tf(Bp[(kk + tg) * BS_S + col]);
                bf[nf][1] = f2tf(Bp[(kk + 4 + tg) * BS_S + col]);
            }
            #pragma unroll
            for (int mf = 0; mf < 2; mf++)
                #pragma unroll
                for (int nf = 0; nf < 8; nf++)
                    mma8(acc[mf][nf], af[mf], bf[nf], acc[mf][nf]);
        }
    }

    #pragma unroll
    for (int mf = 0; mf < 2; mf++) {
        #pragma unroll
        for (int nf = 0; nf < 8; nf++) {
            int col = n0 + wn + nf * 8 + 2 * tg;
            float2 b2 = *(const float2*)&pa.bias[col];
            #pragma unroll
            for (int rr = 0; rr < 2; rr++) {
                int m = m0 + wm + mf * 16 + g + rr * 8;
                float vx = (acc[mf][nf][rr * 2 + 0] + b2.x) * pa.scale;
                float vy = (acc[mf][nf][rr * 2 + 1] + b2.y) * pa.scale;
                if (pa.mode == 0) {
                    *(float2*)&pa.out[m * 1024 + col] = make_float2(vx, vy);
                } else {
                    vx = __uint_as_float(f2tf(vx));
                    vy = __uint_as_float(f2tf(vy));
                    int b = m >> 9, l = m & 511;
                    int h = col >> 6, dh = col & 63;
                    if (pa.mode == 1) {
                        *(float2*)&pa.out[((b * HH + h) * LL + l) * DH + dh] =
                            make_float2(vx, vy);
                    } else {
                        pa.out[((b * HH + h) * DH + dh) * LL + l] = vx;
                        pa.out[((b * HH + h) * DH + dh + 1) * LL + l] = vy;
                    }
                }
            }
        }
    }
}

// ---------------------------------------------------------------------------
// qk: scores[bh][i][j] = q[bh][i][:] . kT[bh][:][j]  (M=N=512, K=64 per bh)
// 64x128 tile, 128 threads, 3-stage cp.async. Operands pre-rounded -> raw bits.
// ---------------------------------------------------------------------------
__global__ __launch_bounds__(128, 4) void qk_tf32(float* __restrict__ scores)
{
    __shared__ __align__(16) unsigned Asq[NSTG][64 * AS_S];
    __shared__ __align__(16) unsigned Bsq[NSTG][16 * BS_S];

    const int NIT = 4;   // K=64 / 16

    int t = threadIdx.x;
    int bh = blockIdx.z;
    const float* __restrict__ Q  = g_q + bh * LL * DH;   // [l][dh]
    const float* __restrict__ KT = g_k + bh * LL * DH;   // [dh][l]
    int m0 = blockIdx.y * 64, n0 = blockIdx.x * 128;
    int wid = t >> 5, lane = t & 31;
    int wm = (wid >> 1) * 32, wn = (wid & 1) * 64;
    int g = lane >> 2, tg = lane & 3;

    int a_r = t >> 2, a_c = (t & 3) * 4;
    int b_r = t >> 5, b_c = (t & 31) * 4;

    const float* a_src = &Q[(m0 + a_r) * DH + a_c];
    const float* k_src = &KT[b_r * LL + n0 + b_c];
    unsigned a_dst = smem_u32(&Asq[0][a_r * AS_S + a_c]);
    unsigned b_dst = smem_u32(&Bsq[0][b_r * BS_S + b_c]);
    const unsigned a_stg = 64 * AS_S * 4;
    const unsigned b_stg = 16 * BS_S * 4;

    float acc[2][8][4];
    #pragma unroll
    for (int i = 0; i < 2; i++)
        #pragma unroll
        for (int j = 0; j < 8; j++)
            #pragma unroll
            for (int e = 0; e < 4; e++) acc[i][j][e] = 0.f;

    #pragma unroll
    for (int s = 0; s < 2; s++) {
        const float* as = a_src + s * 16;
        const float* ks = k_src + s * 16 * LL;
        cpa16(a_dst + s * a_stg,                 as);
        cpa16(a_dst + s * a_stg + 32 * AS_S * 4, as + 32 * DH);
        cpa16(b_dst + s * b_stg,                 ks);
        cpa16(b_dst + s * b_stg + 4 * BS_S * 4,  ks + 4 * LL);
        cpa16(b_dst + s * b_stg + 8 * BS_S * 4,  ks + 8 * LL);
        cpa16(b_dst + s * b_stg + 12 * BS_S * 4, ks + 12 * LL);
        CP_COMMIT();
    }

    for (int i = 0; i < NIT; i++) {
        CP_WAIT1();
        __syncthreads();

        int ki = i + 2;
        if (ki < NIT) {
            unsigned s = (unsigned)(ki % 3);
            const float* as = a_src + ki * 16;
            const float* ks = k_src + ki * 16 * LL;
            cpa16(a_dst + s * a_stg,                 as);
            cpa16(a_dst + s * a_stg + 32 * AS_S * 4, as + 32 * DH);
            cpa16(b_dst + s * b_stg,                 ks);
            cpa16(b_dst + s * b_stg + 4 * BS_S * 4,  ks + 4 * LL);
            cpa16(b_dst + s * b_stg + 8 * BS_S * 4,  ks + 8 * LL);
            cpa16(b_dst + s * b_stg + 12 * BS_S * 4, ks + 12 * LL);
        }
        CP_COMMIT();

        const unsigned* Ap = Asq[i % 3];
        const unsigned* Bp = Bsq[i % 3];

        #pragma unroll
        for (int kk = 0; kk < 16; kk += 8) {
            unsigned af[2][4], bf[8][2];
            #pragma unroll
            for (int mf = 0; mf < 2; mf++) {
                int row = wm + mf * 16 + g;
                af[mf][0] = Ap[row * AS_S + kk + tg];
                af[mf][1] = Ap[(row + 8) * AS_S + kk + tg];
                af[mf][2] = Ap[row * AS_S + kk + 4 + tg];
                af[mf][3] = Ap[(row + 8) * AS_S + kk + 4 + tg];
            }
            #pragma unroll
            for (int nf = 0; nf < 8; nf++) {
                int col = wn + nf * 8 + g;
                bf[nf][0] = Bp[(kk + tg) * BS_S + col];
                bf[nf][1] = Bp[(kk + 4 + tg) * BS_S + col];
            }
            #pragma unroll
            for (int mf = 0; mf < 2; mf++)
                #pragma unroll
                for (int nf = 0; nf < 8; nf++)
                    mma8(acc[mf][nf], af[mf], bf[nf], acc[mf][nf]);
        }
    }

    float* srow = scores + (size_t)bh * LL * LL;
    #pragma unroll
    for (int mf = 0; mf < 2; mf++)
        #pragma unroll
        for (int nf = 0; nf < 8; nf++) {
            int col = n0 + wn + nf * 8 + 2 * tg;
            #pragma unroll
            for (int rr = 0; rr < 2; rr++) {
                int m = m0 + wm + mf * 16 + g + rr * 8;
                *(float2*)&srow[m * LL + col] =
                    make_float2(acc[mf][nf][rr * 2], acc[mf][nf][rr * 2 + 1]);
            }
        }
}

// ---------------------------------------------------------------------------
// Fused ast + mask + softmax. Block (i, b), 128 threads.  (unchanged, proven)
// ---------------------------------------------------------------------------
__global__ __launch_bounds__(128) void astsm_tf32(
    const int* __restrict__ mat, const float* __restrict__ semb,
    const float* __restrict__ vemb, float* __restrict__ attn,
    const unsigned char* __restrict__ mask)
{
    __shared__ __align__(16) unsigned qs[16 * 68];
    __shared__ __align__(16) unsigned pe[128 * 68];
    __shared__ unsigned char mks[512];
    __shared__ float redmx[16 * 4];
    __shared__ float redsm[16 * 4];

    int i = blockIdx.x, b = blockIdx.y;
    int t = threadIdx.x;
    int wid = t >> 5, lane = t & 31;
    int g = lane >> 2, tg = lane & 3;

    for (int idx = t; idx < HH * DH; idx += 128) {
        int h = idx >> 6, d = idx & 63;
        qs[h * 68 + d] = f2tf(g_q[((b * HH + h) * LL + i) * DH + d]);
    }
    *(uchar4*)&mks[t * 4] = *(const uchar4*)&mask[b * LL + t * 4];
    __syncthreads();

    unsigned af[8][4];
    #pragma unroll
    for (int ks = 0; ks < 8; ks++) {
        af[ks][0] = qs[g * 68 + ks * 8 + tg];
        af[ks][1] = qs[(g + 8) * 68 + ks * 8 + tg];
        af[ks][2] = qs[g * 68 + ks * 8 + 4 + tg];
        af[ks][3] = qs[(g + 8) * 68 + ks * 8 + 4 + tg];
    }

    const int* mrow = mat + (b * LL + i) * LL;
    float sc[4][4][4];   // [jt][nf][e]

    for (int jt = 0; jt < 4; jt++) {
        int j0 = jt * 128;
        __syncthreads();
        {
            int j = j0 + t;
            int id = mrow[j];
            const float* e = ((j & 1) ? vemb : semb) + id * DH;
            #pragma unroll
            for (int s = 0; s < 64; s += 4)
                *(uint4*)&pe[t * 68 + s] = cvt4(*(const float4*)&e[s]);
        }
        __syncthreads();

        #pragma unroll
        for (int nf = 0; nf < 4; nf++)
            #pragma unroll
            for (int e = 0; e < 4; e++) sc[jt][nf][e] = 0.f;

        #pragma unroll
        for (int ks = 0; ks < 8; ks++) {
            #pragma unroll
            for (int nf = 0; nf < 4; nf++) {
                int jj = wid * 32 + nf * 8 + g;
                unsigned bf[2];
                bf[0] = pe[jj * 68 + ks * 8 + tg];
                bf[1] = pe[jj * 68 + ks * 8 + 4 + tg];
                mma8(sc[jt][nf], af[ks], bf, sc[jt][nf]);
            }
        }
    }

    size_t base0 = (((size_t)(b * HH + g) * LL + i) * LL);
    size_t base1 = (((size_t)(b * HH + g + 8) * LL + i) * LL);
    #pragma unroll
    for (int jt = 0; jt < 4; jt++)
        #pragma unroll
        for (int nf = 0; nf < 4; nf++) {
            int col = jt * 128 + wid * 32 + nf * 8 + 2 * tg;
            float2 s0 = *(const float2*)&attn[base0 + col];
            float2 s1 = *(const float2*)&attn[base1 + col];
            sc[jt][nf][0] += s0.x; sc[jt][nf][1] += s0.y;
            sc[jt][nf][2] += s1.x; sc[jt][nf][3] += s1.y;
            if (mks[col])     { sc[jt][nf][0] = -1e18f; sc[jt][nf][2] = -1e18f; }
            if (mks[col + 1]) { sc[jt][nf][1] = -1e18f; sc[jt][nf][3] = -1e18f; }
        }

    float mx0 = -1e30f, mx1 = -1e30f;
    #pragma unroll
    for (int jt = 0; jt < 4; jt++)
        #pragma unroll
        for (int nf = 0; nf < 4; nf++) {
            mx0 = fmaxf(mx0, fmaxf(sc[jt][nf][0], sc[jt][nf][1]));
            mx1 = fmaxf(mx1, fmaxf(sc[jt][nf][2], sc[jt][nf][3]));
        }
    #pragma unroll
    for (int o = 1; o <= 2; o <<= 1) {
        mx0 = fmaxf(mx0, __shfl_xor_sync(0xffffffffu, mx0, o));
        mx1 = fmaxf(mx1, __shfl_xor_sync(0xffffffffu, mx1, o));
    }
    if (tg == 0) { redmx[g * 4 + wid] = mx0; redmx[(g + 8) * 4 + wid] = mx1; }
    __syncthreads();
    mx0 = fmaxf(fmaxf(redmx[g * 4 + 0], redmx[g * 4 + 1]),
                fmaxf(redmx[g * 4 + 2], redmx[g * 4 + 3]));
    mx1 = fmaxf(fmaxf(redmx[(g + 8) * 4 + 0], redmx[(g + 8) * 4 + 1]),
                fmaxf(redmx[(g + 8) * 4 + 2], redmx[(g + 8) * 4 + 3]));

    float sm0 = 0.f, sm1 = 0.f;
    #pragma unroll
    for (int jt = 0; jt < 4; jt++)
        #pragma unroll
        for (int nf = 0; nf < 4; nf++) {
            sc[jt][nf][0] = __expf(sc[jt][nf][0] - mx0);
            sc[jt][nf][1] = __expf(sc[jt][nf][1] - mx0);
            sc[jt][nf][2] = __expf(sc[jt][nf][2] - mx1);
            sc[jt][nf][3] = __expf(sc[jt][nf][3] - mx1);
            sm0 += sc[jt][nf][0] + sc[jt][nf][1];
            sm1 += sc[jt][nf][2] + sc[jt][nf][3];
        }
    #pragma unroll
    for (int o = 1; o <= 2; o <<= 1) {
        sm0 += __shfl_xor_sync(0xffffffffu, sm0, o);
        sm1 += __shfl_xor_sync(0xffffffffu, sm1, o);
    }
    if (tg == 0) { redsm[g * 4 + wid] = sm0; redsm[(g + 8) * 4 + wid] = sm1; }
    __syncthreads();
    sm0 = redsm[g * 4 + 0] + redsm[g * 4 + 1] + redsm[g * 4 + 2] + redsm[g * 4 + 3];
    sm1 = redsm[(g + 8) * 4 + 0] + redsm[(g + 8) * 4 + 1] +
          redsm[(g + 8) * 4 + 2] + redsm[(g + 8) * 4 + 3];
    float inv0 = 1.0f / sm0, inv1 = 1.0f / sm1;

    #pragma unroll
    for (int jt = 0; jt < 4; jt++)
        #pragma unroll
        for (int nf = 0; nf < 4; nf++) {
            int col = jt * 128 + wid * 32 + nf * 8 + 2 * tg;
            *(float2*)&attn[base0 + col] =
                make_float2(sc[jt][nf][0] * inv0, sc[jt][nf][1] * inv0);
            *(float2*)&attn[base1 + col] =
                make_float2(sc[jt][nf][2] * inv1, sc[jt][nf][3] * inv1);
        }
}

// ---------------------------------------------------------------------------
// av: ctx[b][l][h*64+d] = sum_j attn[bh][l][j] * v[bh][j][d]
// Per bh: M=512 N=64 K=512. 64x64 tile, 128 threads, BK=16,
// 3-stage cp.async pipeline (29.2KB static smem).
// ---------------------------------------------------------------------------
__global__ __launch_bounds__(128, 4) void av_tf32(const float* __restrict__ attn)
{
    __shared__ __align__(16) float    Asv[NSTG][64 * AS_S];
    __shared__ __align__(16) unsigned Bsv[NSTG][16 * BS64_S];

    const int NIT = 32;   // K=512 / 16

    int t = threadIdx.x;
    int bh = blockIdx.y;
    int m0 = blockIdx.x * 64;
    const float* __restrict__ A = attn + (size_t)bh * LL * LL;
    const float* __restrict__ V = g_v + bh * LL * DH;
    int wid = t >> 5, lane = t & 31;
    int wm = (wid >> 1) * 32, wn = (wid & 1) * 32;
    int g = lane >> 2, tg = lane & 3;

    int a_r = t >> 2, a_c = (t & 3) * 4;   // 0..31 (+32)
    int b_r = t >> 4, b_c = (t & 15) * 4;  // 0..7 (+8)

    const float* a_src = &A[(size_t)(m0 + a_r) * LL + a_c];
    const float* v_src = &V[b_r * DH + b_c];
    unsigned a_dst = smem_u32(&Asv[0][a_r * AS_S + a_c]);
    unsigned b_dst = smem_u32(&Bsv[0][b_r * BS64_S + b_c]);
    const unsigned a_stg = 64 * AS_S * 4;
    const unsigned b_stg = 16 * BS64_S * 4;

    float acc[2][4][4];
    #pragma unroll
    for (int i = 0; i < 2; i++)
        #pragma unroll
        for (int j = 0; j < 4; j++)
            #pragma unroll
            for (int e = 0; e < 4; e++) acc[i][j][e] = 0.f;

    #pragma unroll
    for (int s = 0; s < 2; s++) {
        const float* as = a_src + s * 16;
        const float* vs = v_src + s * 16 * DH;
        cpa16(a_dst + s * a_stg,                  as);
        cpa16(a_dst + s * a_stg + 32 * AS_S * 4,  as + 32 * LL);
        cpa16(b_dst + s * b_stg,                  vs);
        cpa16(b_dst + s * b_stg + 8 * BS64_S * 4, vs + 8 * DH);
        CP_COMMIT();
    }

    for (int i = 0; i < NIT; i++) {
        CP_WAIT1();
        __syncthreads();

        int ki = i + 2;
        if (ki < NIT) {
            unsigned s = (unsigned)(ki % 3);
            const float* as = a_src + ki * 16;
            const float* vs = v_src + ki * 16 * DH;
            cpa16(a_dst + s * a_stg,                  as);
            cpa16(a_dst + s * a_stg + 32 * AS_S * 4,  as + 32 * LL);
            cpa16(b_dst + s * b_stg,                  vs);
            cpa16(b_dst + s * b_stg + 8 * BS64_S * 4, vs + 8 * DH);
        }
        CP_COMMIT();

        const float*    Ap = Asv[i % 3];
        const unsigned* Bp = Bsv[i % 3];

        #pragma unroll
        for (int kk = 0; kk < 16; kk += 8) {
            unsigned af[2][4], bf[4][2];
            #pragma unroll
            for (int mf = 0; mf < 2; mf++) {
                int row = wm + mf * 16 + g;
                af[mf][0] = f2tf(Ap[row * AS_S + kk + tg]);
                af[mf][1] = f2tf(Ap[(row + 8) * AS_S + kk + tg]);
                af[mf][2] = f2tf(Ap[row * AS_S + kk + 4 + tg]);
                af[mf][3] = f2tf(Ap[(row + 8) * AS_S + kk + 4 + tg]);
            }
            #pragma unroll
            for (int nf = 0; nf < 4; nf++) {
                int col = wn + nf * 8 + g;
                bf[nf][0] = Bp[(kk + tg) * BS64_S + col];
                bf[nf][1] = Bp[(kk + 4 + tg) * BS64_S + col];
            }
            #pragma unroll
            for (int mf = 0; mf < 2; mf++)
                #pragma unroll
                for (int nf = 0; nf < 4; nf++)
                    mma8(acc[mf][nf], af[mf], bf[nf], acc[mf][nf]);
        }
    }

    int b = bh >> 4, h = bh & 15;
    #pragma unroll
    for (int mf = 0; mf < 2; mf++)
        #pragma unroll
        for (int nf = 0; nf < 4; nf++) {
            int n = wn + nf * 8 + 2 * tg;
            #pragma unroll
            for (int rr = 0; rr < 2; rr++) {
                int l = m0 + wm + mf * 16 + g + rr * 8;
                float vx = __uint_as_float(f2tf(acc[mf][nf][rr * 2]));
                float vy = __uint_as_float(f2tf(acc[mf][nf][rr * 2 + 1]));
                *(float2*)&g_ctx[((b * LL + l) * DD) + h * DH + n] =
                    make_float2(vx, vy);
            }
        }
}

// ---------------------------------------------------------------------------
extern "C" void kernel_launch(void* const* d_in, const int* in_sizes, int n_in,
                              void* d_out, int out_size)
{
    const float* key   = (const float*)d_in[0];
    const float* value = (const float*)d_in[1];
    const float* query = (const float*)d_in[2];
    const int*   mat   = (const int*)d_in[3];
    const unsigned char* mask = (const unsigned char*)d_in[4];
    const float* Wq = (const float*)d_in[5];
    const float* bq = (const float*)d_in[6];
    const float* Wk = (const float*)d_in[7];
    const float* bk = (const float*)d_in[8];
    const float* Wv = (const float*)d_in[9];
    const float* bv = (const float*)d_in[10];
    const float* Wo = (const float*)d_in[11];
    const float* bo = (const float*)d_in[12];
    const float* semb = (const float*)d_in[13];
    const float* vemb = (const float*)d_in[14];

    float* out  = (float*)d_out;
    float* attn = out + OUT_ELEMS;   // scores buffer, finalized in astsm

    float *q, *k, *v, *ctx;
    cudaGetSymbolAddress((void**)&q,   g_q);
    cudaGetSymbolAddress((void**)&k,   g_k);
    cudaGetSymbolAddress((void**)&v,   g_v);
    cudaGetSymbolAddress((void**)&ctx, g_ctx);

    // Merged Q/K/V projection: one launch, 768 blocks
    PArgs qkv;
    qkv.p[0] = { query, Wq, bq, q, 0.125f, 1 };
    qkv.p[1] = { key,   Wk, bk, k, 1.0f,   2 };
    qkv.p[2] = { value, Wv, bv, v, 1.0f,   1 };
    proj_tf32<<<dim3(8, 32, 3), 128>>>(qkv);

    qk_tf32<<<dim3(4, 8, BH), 128>>>(attn);
    astsm_tf32<<<dim3(LL, BB), 128>>>(mat, semb, vemb, attn, mask);
    av_tf32<<<dim3(8, BH), 128>>>(attn);

    PArgs oarg;
    oarg.p[0] = { ctx, Wo, bo, out, 1.0f, 0 };
    oarg.p[1] = oarg.p[0];
    oarg.p[2] = oarg.p[0];
    proj_tf32<<<dim3(8, 32, 1), 128>>>(oarg);
}

// round 15
// speedup vs baseline: 1.1416x; 1.0620x over previous
#include <cuda_runtime.h>

// Problem constants
#define BB 4
#define LL 512
#define DD 1024
#define HH 16
#define DH 64
#define BH (BB*HH)            // 64
#define OUT_ELEMS (BB*LL*DD)  // 2097152

// Scratch (no allocations allowed -> __device__ globals)
// Values stored tf32-rounded (bit patterns of cvt.rna.tf32) so consumers can
// feed smem bits directly to mma without per-fragment cvt.
__device__ float g_q[BB*HH*LL*DH];    // [b][h][l][dh]   (rounded)
__device__ float g_k[BB*HH*LL*DH];    // [b][h][dh][l]   (rounded, transposed)
__device__ float g_v[BB*HH*LL*DH];    // [b][h][l][dh]   (rounded)
__device__ float g_ctx[BB*LL*DD];     // (rounded)

// ---------------------------------------------------------------------------
// tf32 helpers (mma.sync m16n8k8, row.col, f32 accum)
// ---------------------------------------------------------------------------
__device__ __forceinline__ unsigned f2tf(float x) {
    unsigned y; asm("cvt.rna.tf32.f32 %0, %1;" : "=r"(y) : "f"(x)); return y;
}
__device__ __forceinline__ void mma8(float* d, const unsigned* a,
                                     const unsigned* b, const float* c) {
    asm volatile(
        "mma.sync.aligned.m16n8k8.row.col.f32.tf32.tf32.f32 "
        "{%0,%1,%2,%3}, {%4,%5,%6,%7}, {%8,%9}, {%10,%11,%12,%13};"
        : "=f"(d[0]), "=f"(d[1]), "=f"(d[2]), "=f"(d[3])
        : "r"(a[0]), "r"(a[1]), "r"(a[2]), "r"(a[3]),
          "r"(b[0]), "r"(b[1]),
          "f"(c[0]), "f"(c[1]), "f"(c[2]), "f"(c[3]));
}

__device__ __forceinline__ unsigned smem_u32(const void* p) {
    return (unsigned)__cvta_generic_to_shared(p);
}
__device__ __forceinline__ void cpa16(unsigned dst, const void* src) {
    asm volatile("cp.async.cg.shared.global [%0], [%1], 16;" :: "r"(dst), "l"(src));
}
#define CP_COMMIT() asm volatile("cp.async.commit_group;")
#define CP_WAIT1()  asm volatile("cp.async.wait_group 1;")
#define CP_WAIT2()  asm volatile("cp.async.wait_group 2;")

// Smem strides (elements), conflict-free fragment reads:
//   As stride 20, Bs stride 136, Bs64 stride 72 (banks all-distinct per warp)
#define AS_S 20
#define BS_S 136
#define BS64_S 72
#define NSTG 3
#define AV_NSTG 4

struct PArg { const float* A; const float* W; const float* bias;
              float* out; float scale; int mode; };
struct PArgs { PArg p[3]; };

// ---------------------------------------------------------------------------
// Projection GEMM: C = A(2048x1024) @ W(1024x1024) + bias, scale.
// mode 0: out[m][n] raw; mode 1: [b][h][l][dh] rounded; mode 2: [b][h][dh][l].
// 64x128 tile, BK=16, 128 threads (4 warps, 2m x 2n, warp tile 32x64),
// 3-stage cp.async pipeline (wait_group 1), static smem 41.5KB.
// ---------------------------------------------------------------------------
__global__ __launch_bounds__(128, 4) void proj_tf32(PArgs args)
{
    __shared__ __align__(16) float Asf[NSTG][64 * AS_S];
    __shared__ __align__(16) float Bsf[NSTG][16 * BS_S];

    const int K = 1024, N = 1024, NIT = 64;

    PArg pa = args.p[blockIdx.z];
    const float* __restrict__ A = pa.A;
    const float* __restrict__ W = pa.W;

    int t = threadIdx.x;
    int m0 = blockIdx.y * 64, n0 = blockIdx.x * 128;
    int wid = t >> 5, lane = t & 31;
    int wm = (wid >> 1) * 32, wn = (wid & 1) * 64;
    int g = lane >> 2, tg = lane & 3;

    int a_r = t >> 2;            // 0..31 (+32)
    int a_c = (t & 3) * 4;
    int b_r = t >> 5;            // 0..3 (+4,+8,+12)
    int b_c = (t & 31) * 4;

    const float* a_src = &A[(m0 + a_r) * K + a_c];
    const float* w_src = &W[b_r * N + n0 + b_c];
    unsigned a_dst = smem_u32(&Asf[0][a_r * AS_S + a_c]);
    unsigned b_dst = smem_u32(&Bsf[0][b_r * BS_S + b_c]);
    const unsigned a_stg = 64 * AS_S * 4;
    const unsigned b_stg = 16 * BS_S * 4;

    float acc[2][8][4];
    #pragma unroll
    for (int i = 0; i < 2; i++)
        #pragma unroll
        for (int j = 0; j < 8; j++)
            #pragma unroll
            for (int e = 0; e < 4; e++) acc[i][j][e] = 0.f;

    // prologue: tiles 0,1 -> stages 0,1 (two groups in flight)
    #pragma unroll
    for (int s = 0; s < 2; s++) {
        const float* as = a_src + s * 16;
        const float* ws = w_src + s * 16 * N;
        cpa16(a_dst + s * a_stg,                 as);
        cpa16(a_dst + s * a_stg + 32 * AS_S * 4, as + 32 * K);
        cpa16(b_dst + s * b_stg,                 ws);
        cpa16(b_dst + s * b_stg + 4 * BS_S * 4,  ws + 4 * N);
        cpa16(b_dst + s * b_stg + 8 * BS_S * 4,  ws + 8 * N);
        cpa16(b_dst + s * b_stg + 12 * BS_S * 4, ws + 12 * N);
        CP_COMMIT();
    }

    for (int i = 0; i < NIT; i++) {
        CP_WAIT1();          // stage i arrived (exactly 2 groups pending before)
        __syncthreads();     // ...and stage (i+2)%3 free of readers

        int ki = i + 2;
        if (ki < NIT) {
            unsigned s = (unsigned)(ki % 3);
            const float* as = a_src + ki * 16;
            const float* ws = w_src + ki * 16 * N;
            cpa16(a_dst + s * a_stg,                 as);
            cpa16(a_dst + s * a_stg + 32 * AS_S * 4, as + 32 * K);
            cpa16(b_dst + s * b_stg,                 ws);
            cpa16(b_dst + s * b_stg + 4 * BS_S * 4,  ws + 4 * N);
            cpa16(b_dst + s * b_stg + 8 * BS_S * 4,  ws + 8 * N);
            cpa16(b_dst + s * b_stg + 12 * BS_S * 4, ws + 12 * N);
        }
        CP_COMMIT();         // unconditional: keeps pending-group count = 2

        const float* Ap = Asf[i % 3];
        const float* Bp = Bsf[i % 3];

        #pragma unroll
        for (int kk = 0; kk < 16; kk += 8) {
            unsigned af[2][4], bf[8][2];
            #pragma unroll
            for (int mf = 0; mf < 2; mf++) {
                int row = wm + mf * 16 + g;
                af[mf][0] = f2tf(Ap[row * AS_S + kk + tg]);
                af[mf][1] = f2tf(Ap[(row + 8) * AS_S + kk + tg]);
                af[mf][2] = f2tf(Ap[row * AS_S + kk + 4 + tg]);
                af[mf][3] = f2tf(Ap[(row + 8) * AS_S + kk + 4 + tg]);
            }
            #pragma unroll
            for (int nf = 0; nf < 8; nf++) {
                int col = wn + nf * 8 + g;
                bf[nf][0] = f2tf(Bp[(kk + tg) * BS_S + col]);
                bf[nf][1] = f2tf(Bp[(kk + 4 + tg) * BS_S + col]);
            }
            #pragma unroll
            for (int mf = 0; mf < 2; mf++)
                #pragma unroll
                for (int nf = 0; nf < 8; nf++)
                    mma8(acc[mf][nf], af[mf], bf[nf], acc[mf][nf]);
        }
    }

    #pragma unroll
    for (int mf = 0; mf < 2; mf++) {
        #pragma unroll
        for (int nf = 0; nf < 8; nf++) {
            int col = n0 + wn + nf * 8 + 2 * tg;
            float2 b2 = *(const float2*)&pa.bias[col];
            #pragma unroll
            for (int rr = 0; rr < 2; rr++) {
                int m = m0 + wm + mf * 16 + g + rr * 8;
                float vx = (acc[mf][nf][rr * 2 + 0] + b2.x) * pa.scale;
                float vy = (acc[mf][nf][rr * 2 + 1] + b2.y) * pa.scale;
                if (pa.mode == 0) {
                    *(float2*)&pa.out[m * 1024 + col] = make_float2(vx, vy);
                } else {
                    vx = __uint_as_float(f2tf(vx));
                    vy = __uint_as_float(f2tf(vy));
                    int b = m >> 9, l = m & 511;
                    int h = col >> 6, dh = col & 63;
                    if (pa.mode == 1) {
                        *(float2*)&pa.out[((b * HH + h) * LL + l) * DH + dh] =
                            make_float2(vx, vy);
                    } else {
                        pa.out[((b * HH + h) * DH + dh) * LL + l] = vx;
                        pa.out[((b * HH + h) * DH + dh + 1) * LL + l] = vy;
                    }
                }
            }
        }
    }
}

// ---------------------------------------------------------------------------
// qk: scores[bh][i][j] = q[bh][i][:] . kT[bh][:][j]  (M=N=512, K=64 per bh)
// 64x128 tile, 128 threads, 3-stage cp.async. Operands pre-rounded -> raw bits.
// ---------------------------------------------------------------------------
__global__ __launch_bounds__(128, 4) void qk_tf32(float* __restrict__ scores)
{
    __shared__ __align__(16) unsigned Asq[NSTG][64 * AS_S];
    __shared__ __align__(16) unsigned Bsq[NSTG][16 * BS_S];

    const int NIT = 4;   // K=64 / 16

    int t = threadIdx.x;
    int bh = blockIdx.z;
    const float* __restrict__ Q  = g_q + bh * LL * DH;   // [l][dh]
    const float* __restrict__ KT = g_k + bh * LL * DH;   // [dh][l]
    int m0 = blockIdx.y * 64, n0 = blockIdx.x * 128;
    int wid = t >> 5, lane = t & 31;
    int wm = (wid >> 1) * 32, wn = (wid & 1) * 64;
    int g = lane >> 2, tg = lane & 3;

    int a_r = t >> 2, a_c = (t & 3) * 4;
    int b_r = t >> 5, b_c = (t & 31) * 4;

    const float* a_src = &Q[(m0 + a_r) * DH + a_c];
    const float* k_src = &KT[b_r * LL + n0 + b_c];
    unsigned a_dst = smem_u32(&Asq[0][a_r * AS_S + a_c]);
    unsigned b_dst = smem_u32(&Bsq[0][b_r * BS_S + b_c]);
    const unsigned a_stg = 64 * AS_S * 4;
    const unsigned b_stg = 16 * BS_S * 4;

    float acc[2][8][4];
    #pragma unroll
    for (int i = 0; i < 2; i++)
        #pragma unroll
        for (int j = 0; j < 8; j++)
            #pragma unroll
            for (int e = 0; e < 4; e++) acc[i][j][e] = 0.f;

    #pragma unroll
    for (int s = 0; s < 2; s++) {
        const float* as = a_src + s * 16;
        const float* ks = k_src + s * 16 * LL;
        cpa16(a_dst + s * a_stg,                 as);
        cpa16(a_dst + s * a_stg + 32 * AS_S * 4, as + 32 * DH);
        cpa16(b_dst + s * b_stg,                 ks);
        cpa16(b_dst + s * b_stg + 4 * BS_S * 4,  ks + 4 * LL);
        cpa16(b_dst + s * b_stg + 8 * BS_S * 4,  ks + 8 * LL);
        cpa16(b_dst + s * b_stg + 12 * BS_S * 4, ks + 12 * LL);
        CP_COMMIT();
    }

    for (int i = 0; i < NIT; i++) {
        CP_WAIT1();
        __syncthreads();

        int ki = i + 2;
        if (ki < NIT) {
            unsigned s = (unsigned)(ki % 3);
            const float* as = a_src + ki * 16;
            const float* ks = k_src + ki * 16 * LL;
            cpa16(a_dst + s * a_stg,                 as);
            cpa16(a_dst + s * a_stg + 32 * AS_S * 4, as + 32 * DH);
            cpa16(b_dst + s * b_stg,                 ks);
            cpa16(b_dst + s * b_stg + 4 * BS_S * 4,  ks + 4 * LL);
            cpa16(b_dst + s * b_stg + 8 * BS_S * 4,  ks + 8 * LL);
            cpa16(b_dst + s * b_stg + 12 * BS_S * 4, ks + 12 * LL);
        }
        CP_COMMIT();

        const unsigned* Ap = Asq[i % 3];
        const unsigned* Bp = Bsq[i % 3];

        #pragma unroll
        for (int kk = 0; kk < 16; kk += 8) {
            unsigned af[2][4], bf[8][2];
            #pragma unroll
            for (int mf = 0; mf < 2; mf++) {
                int row = wm + mf * 16 + g;
                af[mf][0] = Ap[row * AS_S + kk + tg];
                af[mf][1] = Ap[(row + 8) * AS_S + kk + tg];
                af[mf][2] = Ap[row * AS_S + kk + 4 + tg];
                af[mf][3] = Ap[(row + 8) * AS_S + kk + 4 + tg];
            }
            #pragma unroll
            for (int nf = 0; nf < 8; nf++) {
                int col = wn + nf * 8 + g;
                bf[nf][0] = Bp[(kk + tg) * BS_S + col];
                bf[nf][1] = Bp[(kk + 4 + tg) * BS_S + col];
            }
            #pragma unroll
            for (int mf = 0; mf < 2; mf++)
                #pragma unroll
                for (int nf = 0; nf < 8; nf++)
                    mma8(acc[mf][nf], af[mf], bf[nf], acc[mf][nf]);
        }
    }

    float* srow = scores + (size_t)bh * LL * LL;
    #pragma unroll
    for (int mf = 0; mf < 2; mf++)
        #pragma unroll
        for (int nf = 0; nf < 8; nf++) {
            int col = n0 + wn + nf * 8 + 2 * tg;
            #pragma unroll
            for (int rr = 0; rr < 2; rr++) {
                int m = m0 + wm + mf * 16 + g + rr * 8;
                *(float2*)&srow[m * LL + col] =
                    make_float2(acc[mf][nf][rr * 2], acc[mf][nf][rr * 2 + 1]);
            }
        }
}

// ---------------------------------------------------------------------------
// Fused ast + mask + softmax. Block (i, b), 128 threads.
// NEW: gathers pipelined via per-thread cp.async, 8 j-tiles of 64, double-
// buffered pe (raw fp32, cvt at fragment read). Same arithmetic per element.
// Thread (wid, g, tg) owns rows h=g and h=g+8,
// cols jt*64 + wid*16 + nf*8 + 2tg + {0,1}, jt=0..7, nf=0..1.
// ---------------------------------------------------------------------------
__global__ __launch_bounds__(128) void astsm_tf32(
    const int* __restrict__ mat, const float* __restrict__ semb,
    const float* __restrict__ vemb, float* __restrict__ attn,
    const unsigned char* __restrict__ mask)
{
    __shared__ __align__(16) unsigned qs[16 * 68];
    __shared__ __align__(16) float pe[2][64 * 68];   // raw fp32 gathered tiles
    __shared__ unsigned char mks[512];
    __shared__ float redmx[16 * 4];
    __shared__ float redsm[16 * 4];

    int i = blockIdx.x, b = blockIdx.y;
    int t = threadIdx.x;
    int wid = t >> 5, lane = t & 31;
    int g = lane >> 2, tg = lane & 3;

    for (int idx = t; idx < HH * DH; idx += 128) {
        int h = idx >> 6, d = idx & 63;
        qs[h * 68 + d] = f2tf(g_q[((b * HH + h) * LL + i) * DH + d]);
    }
    *(uchar4*)&mks[t * 4] = *(const uchar4*)&mask[b * LL + t * 4];

    // gather assignment: 64 rows/tile, 2 threads per row (halves of 32 floats)
    const int* mrow = mat + (b * LL + i) * LL;
    int grow = t & 63;            // row within tile
    int ghalf = t >> 6;           // 0/1
    const float* gtbl = (grow & 1) ? vemb : semb;   // parity of j = parity of grow
    unsigned pdst = smem_u32(&pe[0][grow * 68 + ghalf * 32]);
    const unsigned PE_STG = 64 * 68 * 4;

    // prologue: tiles 0,1
    #pragma unroll
    for (int s = 0; s < 2; s++) {
        int id = mrow[s * 64 + grow];
        const float* src = gtbl + (size_t)id * DH + ghalf * 32;
        #pragma unroll
        for (int c = 0; c < 8; c++)
            cpa16(pdst + (unsigned)s * PE_STG + c * 16, src + c * 4);
        CP_COMMIT();
    }
    __syncthreads();   // qs/mks visible

    unsigned af[8][4];
    #pragma unroll
    for (int ks = 0; ks < 8; ks++) {
        af[ks][0] = qs[g * 68 + ks * 8 + tg];
        af[ks][1] = qs[(g + 8) * 68 + ks * 8 + tg];
        af[ks][2] = qs[g * 68 + ks * 8 + 4 + tg];
        af[ks][3] = qs[(g + 8) * 68 + ks * 8 + 4 + tg];
    }

    float sc[8][2][4];   // [jt][nf][e]

    for (int jt = 0; jt < 8; jt++) {
        CP_WAIT1();        // tile jt's copies (this thread) done
        __syncthreads();   // all threads' copies of tile jt visible

        const float* Pp = pe[jt & 1];

        #pragma unroll
        for (int nf = 0; nf < 2; nf++)
            #pragma unroll
            for (int e = 0; e < 4; e++) sc[jt][nf][e] = 0.f;

        #pragma unroll
        for (int ks = 0; ks < 8; ks++) {
            #pragma unroll
            for (int nf = 0; nf < 2; nf++) {
                int jj = wid * 16 + nf * 8 + g;
                unsigned bf[2];
                bf[0] = f2tf(Pp[jj * 68 + ks * 8 + tg]);
                bf[1] = f2tf(Pp[jj * 68 + ks * 8 + 4 + tg]);
                mma8(sc[jt][nf], af[ks], bf, sc[jt][nf]);
            }
        }

        __syncthreads();   // all warps done reading pe[jt&1] before overwrite
        int kt = jt + 2;
        if (kt < 8) {
            int id = mrow[kt * 64 + grow];
            const float* src = gtbl + (size_t)id * DH + ghalf * 32;
            unsigned dst = pdst + (unsigned)(kt & 1) * PE_STG;
            #pragma unroll
            for (int c = 0; c < 8; c++)
                cpa16(dst + c * 16, src + c * 4);
        }
        CP_COMMIT();       // unconditional: keeps group accounting uniform
    }

    // Add qk scores and apply mask
    size_t base0 = (((size_t)(b * HH + g) * LL + i) * LL);
    size_t base1 = (((size_t)(b * HH + g + 8) * LL + i) * LL);
    #pragma unroll
    for (int jt = 0; jt < 8; jt++)
        #pragma unroll
        for (int nf = 0; nf < 2; nf++) {
            int col = jt * 64 + wid * 16 + nf * 8 + 2 * tg;
            float2 s0 = *(const float2*)&attn[base0 + col];
            float2 s1 = *(const float2*)&attn[base1 + col];
            sc[jt][nf][0] += s0.x; sc[jt][nf][1] += s0.y;
            sc[jt][nf][2] += s1.x; sc[jt][nf][3] += s1.y;
            if (mks[col])     { sc[jt][nf][0] = -1e18f; sc[jt][nf][2] = -1e18f; }
            if (mks[col + 1]) { sc[jt][nf][1] = -1e18f; sc[jt][nf][3] = -1e18f; }
        }

    float mx0 = -1e30f, mx1 = -1e30f;
    #pragma unroll
    for (int jt = 0; jt < 8; jt++)
        #pragma unroll
        for (int nf = 0; nf < 2; nf++) {
            mx0 = fmaxf(mx0, fmaxf(sc[jt][nf][0], sc[jt][nf][1]));
            mx1 = fmaxf(mx1, fmaxf(sc[jt][nf][2], sc[jt][nf][3]));
        }
    #pragma unroll
    for (int o = 1; o <= 2; o <<= 1) {
        mx0 = fmaxf(mx0, __shfl_xor_sync(0xffffffffu, mx0, o));
        mx1 = fmaxf(mx1, __shfl_xor_sync(0xffffffffu, mx1, o));
    }
    if (tg == 0) { redmx[g * 4 + wid] = mx0; redmx[(g + 8) * 4 + wid] = mx1; }
    __syncthreads();
    mx0 = fmaxf(fmaxf(redmx[g * 4 + 0], redmx[g * 4 + 1]),
                fmaxf(redmx[g * 4 + 2], redmx[g * 4 + 3]));
    mx1 = fmaxf(fmaxf(redmx[(g + 8) * 4 + 0], redmx[(g + 8) * 4 + 1]),
                fmaxf(redmx[(g + 8) * 4 + 2], redmx[(g + 8) * 4 + 3]));

    float sm0 = 0.f, sm1 = 0.f;
    #pragma unroll
    for (int jt = 0; jt < 8; jt++)
        #pragma unroll
        for (int nf = 0; nf < 2; nf++) {
            sc[jt][nf][0] = __expf(sc[jt][nf][0] - mx0);
            sc[jt][nf][1] = __expf(sc[jt][nf][1] - mx0);
            sc[jt][nf][2] = __expf(sc[jt][nf][2] - mx1);
            sc[jt][nf][3] = __expf(sc[jt][nf][3] - mx1);
            sm0 += sc[jt][nf][0] + sc[jt][nf][1];
            sm1 += sc[jt][nf][2] + sc[jt][nf][3];
        }
    #pragma unroll
    for (int o = 1; o <= 2; o <<= 1) {
        sm0 += __shfl_xor_sync(0xffffffffu, sm0, o);
        sm1 += __shfl_xor_sync(0xffffffffu, sm1, o);
    }
    if (tg == 0) { redsm[g * 4 + wid] = sm0; redsm[(g + 8) * 4 + wid] = sm1; }
    __syncthreads();
    sm0 = redsm[g * 4 + 0] + redsm[g * 4 + 1] + redsm[g * 4 + 2] + redsm[g * 4 + 3];
    sm1 = redsm[(g + 8) * 4 + 0] + redsm[(g + 8) * 4 + 1] +
          redsm[(g + 8) * 4 + 2] + redsm[(g + 8) * 4 + 3];
    float inv0 = 1.0f / sm0, inv1 = 1.0f / sm1;

    #pragma unroll
    for (int jt = 0; jt < 8; jt++)
        #pragma unroll
        for (int nf = 0; nf < 2; nf++) {
            int col = jt * 64 + wid * 16 + nf * 8 + 2 * tg;
            *(float2*)&attn[base0 + col] =
                make_float2(sc[jt][nf][0] * inv0, sc[jt][nf][1] * inv0);
            *(float2*)&attn[base1 + col] =
                make_float2(sc[jt][nf][2] * inv1, sc[jt][nf][3] * inv1);
        }
}

// ---------------------------------------------------------------------------
// av: ctx[b][l][h*64+d] = sum_j attn[bh][l][j] * v[bh][j][d]
// Per bh: M=512 N=64 K=512. 64x64 tile, 128 threads, BK=16,
// 4-stage cp.async pipeline (38.9KB static smem).
// ---------------------------------------------------------------------------
__global__ __launch_bounds__(128, 4) void av_tf32(const float* __restrict__ attn)
{
    __shared__ __align__(16) float    Asv[AV_NSTG][64 * AS_S];
    __shared__ __align__(16) unsigned Bsv[AV_NSTG][16 * BS64_S];

    const int NIT = 32;   // K=512 / 16

    int t = threadIdx.x;
    int bh = blockIdx.y;
    int m0 = blockIdx.x * 64;
    const float* __restrict__ A = attn + (size_t)bh * LL * LL;
    const float* __restrict__ V = g_v + bh * LL * DH;
    int wid = t >> 5, lane = t & 31;
    int wm = (wid >> 1) * 32, wn = (wid & 1) * 32;
    int g = lane >> 2, tg = lane & 3;

    int a_r = t >> 2, a_c = (t & 3) * 4;   // 0..31 (+32)
    int b_r = t >> 4, b_c = (t & 15) * 4;  // 0..7 (+8)

    const float* a_src = &A[(size_t)(m0 + a_r) * LL + a_c];
    const float* v_src = &V[b_r * DH + b_c];
    unsigned a_dst = smem_u32(&Asv[0][a_r * AS_S + a_c]);
    unsigned b_dst = smem_u32(&Bsv[0][b_r * BS64_S + b_c]);
    const unsigned a_stg = 64 * AS_S * 4;
    const unsigned b_stg = 16 * BS64_S * 4;

    float acc[2][4][4];
    #pragma unroll
    for (int i = 0; i < 2; i++)
        #pragma unroll
        for (int j = 0; j < 4; j++)
            #pragma unroll
            for (int e = 0; e < 4; e++) acc[i][j][e] = 0.f;

    #pragma unroll
    for (int s = 0; s < 3; s++) {
        const float* as = a_src + s * 16;
        const float* vs = v_src + s * 16 * DH;
        cpa16(a_dst + s * a_stg,                  as);
        cpa16(a_dst + s * a_stg + 32 * AS_S * 4,  as + 32 * LL);
        cpa16(b_dst + s * b_stg,                  vs);
        cpa16(b_dst + s * b_stg + 8 * BS64_S * 4, vs + 8 * DH);
        CP_COMMIT();
    }

    for (int i = 0; i < NIT; i++) {
        CP_WAIT2();          // stage i arrived (3 groups pending before)
        __syncthreads();     // stage (i+3)%4 free of readers (read in iter i-1)

        int ki = i + 3;
        if (ki < NIT) {
            unsigned s = (unsigned)(ki % 4);
            const float* as = a_src + ki * 16;
            const float* vs = v_src + ki * 16 * DH;
            cpa16(a_dst + s * a_stg,                  as);
            cpa16(a_dst + s * a_stg + 32 * AS_S * 4,  as + 32 * LL);
            cpa16(b_dst + s * b_stg,                  vs);
            cpa16(b_dst + s * b_stg + 8 * BS64_S * 4, vs + 8 * DH);
        }
        CP_COMMIT();

        const float*    Ap = Asv[i % 4];
        const unsigned* Bp = Bsv[i % 4];

        #pragma unroll
        for (int kk = 0; kk < 16; kk += 8) {
            unsigned af[2][4], bf[4][2];
            #pragma unroll
            for (int mf = 0; mf < 2; mf++) {
                int row = wm + mf * 16 + g;
                af[mf][0] = f2tf(Ap[row * AS_S + kk + tg]);
                af[mf][1] = f2tf(Ap[(row + 8) * AS_S + kk + tg]);
                af[mf][2] = f2tf(Ap[row * AS_S + kk + 4 + tg]);
                af[mf][3] = f2tf(Ap[(row + 8) * AS_S + kk + 4 + tg]);
            }
            #pragma unroll
            for (int nf = 0; nf < 4; nf++) {
                int col = wn + nf * 8 + g;
                bf[nf][0] = Bp[(kk + tg) * BS64_S + col];
                bf[nf][1] = Bp[(kk + 4 + tg) * BS64_S + col];
            }
            #pragma unroll
            for (int mf = 0; mf < 2; mf++)
                #pragma unroll
                for (int nf = 0; nf < 4; nf++)
                    mma8(acc[mf][nf], af[mf], bf[nf], acc[mf][nf]);
        }
    }

    int b = bh >> 4, h = bh & 15;
    #pragma unroll
    for (int mf = 0; mf < 2; mf++)
        #pragma unroll
        for (int nf = 0; nf < 4; nf++) {
            int n = wn + nf * 8 + 2 * tg;
            #pragma unroll
            for (int rr = 0; rr < 2; rr++) {
                int l = m0 + wm + mf * 16 + g + rr * 8;
                float vx = __uint_as_float(f2tf(acc[mf][nf][rr * 2]));
                float vy = __uint_as_float(f2tf(acc[mf][nf][rr * 2 + 1]));
                *(float2*)&g_ctx[((b * LL + l) * DD) + h * DH + n] =
                    make_float2(vx, vy);
            }
        }
}

// ---------------------------------------------------------------------------
extern "C" void kernel_launch(void* const* d_in, const int* in_sizes, int n_in,
                              void* d_out, int out_size)
{
    const float* key   = (const float*)d_in[0];
    const float* value = (const float*)d_in[1];
    const float* query = (const float*)d_in[2];
    const int*   mat   = (const int*)d_in[3];
    const unsigned char* mask = (const unsigned char*)d_in[4];
    const float* Wq = (const float*)d_in[5];
    const float* bq = (const float*)d_in[6];
    const float* Wk = (const float*)d_in[7];
    const float* bk = (const float*)d_in[8];
    const float* Wv = (const float*)d_in[9];
    const float* bv = (const float*)d_in[10];
    const float* Wo = (const float*)d_in[11];
    const float* bo = (const float*)d_in[12];
    const float* semb = (const float*)d_in[13];
    const float* vemb = (const float*)d_in[14];

    float* out  = (float*)d_out;
    float* attn = out + OUT_ELEMS;   // scores buffer, finalized in astsm

    float *q, *k, *v, *ctx;
    cudaGetSymbolAddress((void**)&q,   g_q);
    cudaGetSymbolAddress((void**)&k,   g_k);
    cudaGetSymbolAddress((void**)&v,   g_v);
    cudaGetSymbolAddress((void**)&ctx, g_ctx);

    // Merged Q/K/V projection: one launch, 768 blocks
    PArgs qkv;
    qkv.p[0] = { query, Wq, bq, q, 0.125f, 1 };
    qkv.p[1] = { key,   Wk, bk, k, 1.0f,   2 };
    qkv.p[2] = { value, Wv, bv, v, 1.0f,   1 };
    proj_tf32<<<dim3(8, 32, 3), 128>>>(qkv);

    qk_tf32<<<dim3(4, 8, BH), 128>>>(attn);
    astsm_tf32<<<dim3(LL, BB), 128>>>(mat, semb, vemb, attn, mask);
    av_tf32<<<dim3(8, BH), 128>>>(attn);

    PArgs oarg;
    oarg.p[0] = { ctx, Wo, bo, out, 1.0f, 0 };
    oarg.p[1] = oarg.p[0];
    oarg.p[2] = oarg.p[0];
    proj_tf32<<<dim3(8, 32, 1), 128>>>(oarg);
}